// round 12
// baseline (speedup 1.0000x reference)
#include <cuda_runtime.h>
#include <cuda_bf16.h>
#include <math.h>
#include <stdint.h>

#define DMODEL 1024
#define NHEADS 16
#define DKH    64
#define BATCH  4
#define SEQ    2048
#define MR     (BATCH * SEQ)   // 8192 rows
#define DD     (DMODEL * DMODEL)

// 1/sqrt(d_k) * log2(e): folded into Q so softmax can use ex2.approx
#define QSCALE 0.180336880111120426f

// ---------------- scratch (allocation-free rule: __device__ globals) -------
static __device__ __nv_bfloat16 g_xh[(size_t)MR * DMODEL];
static __device__ __nv_bfloat16 g_xl[(size_t)MR * DMODEL];
static __device__ __nv_bfloat16 g_wh[(size_t)4 * DD];
static __device__ __nv_bfloat16 g_wl[(size_t)4 * DD];
static __device__ __nv_bfloat16 g_qh[(size_t)MR * DMODEL];
static __device__ __nv_bfloat16 g_ql[(size_t)MR * DMODEL];
static __device__ __nv_bfloat16 g_kh[(size_t)MR * DMODEL];
static __device__ __nv_bfloat16 g_kl[(size_t)MR * DMODEL];
static __device__ __nv_bfloat16 g_vh[(size_t)MR * DMODEL];
static __device__ __nv_bfloat16 g_vl[(size_t)MR * DMODEL];
static __device__ __nv_bfloat16 g_ah[(size_t)MR * DMODEL];
static __device__ __nv_bfloat16 g_al[(size_t)MR * DMODEL];

// ---------------- PTX helpers (baseline, legal on compute_103) -------------
__device__ __forceinline__ uint32_t smem_u32(const void* p) {
    uint32_t a;
    asm("{ .reg .u64 t; cvta.to.shared.u64 t, %1; cvt.u32.u64 %0, t; }"
        : "=r"(a) : "l"(p));
    return a;
}

// single-MUFU base-2 exponential (independent of fast-math flags)
__device__ __forceinline__ float fexp2(float x) {
    float y;
    asm("ex2.approx.ftz.f32 %0, %1;" : "=f"(y) : "f"(x));
    return y;
}

__device__ __forceinline__ void cp16(uint32_t dst, const void* src) {
    asm volatile("cp.async.cg.shared.global [%0], [%1], 16;\n"
                 :: "r"(dst), "l"(src) : "memory");
}
#define CP_COMMIT() asm volatile("cp.async.commit_group;\n" ::: "memory")
#define CP_WAIT(n)  asm volatile("cp.async.wait_group %0;\n" :: "n"(n) : "memory")

__device__ __forceinline__ void ldm4(uint32_t* r, uint32_t addr) {
    asm volatile("ldmatrix.sync.aligned.m8n8.x4.shared.b16 {%0,%1,%2,%3}, [%4];"
                 : "=r"(r[0]), "=r"(r[1]), "=r"(r[2]), "=r"(r[3]) : "r"(addr));
}

__device__ __forceinline__ void ldm4t(uint32_t* r, uint32_t addr) {
    asm volatile("ldmatrix.sync.aligned.m8n8.x4.trans.shared.b16 {%0,%1,%2,%3}, [%4];"
                 : "=r"(r[0]), "=r"(r[1]), "=r"(r[2]), "=r"(r[3]) : "r"(addr));
}

__device__ __forceinline__ void mma_bf16(float* c, const uint32_t* a,
                                         uint32_t b0, uint32_t b1) {
    asm volatile(
        "mma.sync.aligned.m16n8k16.row.col.f32.bf16.bf16.f32 "
        "{%0,%1,%2,%3}, {%4,%5,%6,%7}, {%8,%9}, {%0,%1,%2,%3};"
        : "+f"(c[0]), "+f"(c[1]), "+f"(c[2]), "+f"(c[3])
        : "r"(a[0]), "r"(a[1]), "r"(a[2]), "r"(a[3]), "r"(b0), "r"(b1));
}

// split fp32 pair into packed bf16 hi (truncated) + bf16 lo (rn of residual)
__device__ __forceinline__ void split2(float v0, float v1, uint32_t& h, uint32_t& l) {
    uint32_t b0 = __float_as_uint(v0), b1 = __float_as_uint(v1);
    h = __byte_perm(b0, b1, 0x7632);
    float r0 = v0 - __uint_as_float(b0 & 0xFFFF0000u);
    float r1 = v1 - __uint_as_float(b1 & 0xFFFF0000u);
    asm("cvt.rn.bf16x2.f32 %0, %1, %2;" : "=r"(l) : "f"(r1), "f"(r0));
}

// SW128 swizzle for 128B rows
#define SWZ128(o) ((o) ^ (((o) >> 3) & 0x70))
// swizzle for 64B rows
__device__ __forceinline__ uint32_t swz64(int row, int c16) {
    return (uint32_t)(row * 64 + ((c16 ^ ((row >> 1) & 3)) << 4));
}

// ---------------- fp32 -> (bf16 hi, bf16 lo) conversion --------------------
__global__ __launch_bounds__(256) void cvt_hilo(
    const float* __restrict__ in,
    __nv_bfloat16* __restrict__ hi, __nv_bfloat16* __restrict__ lo, int n4)
{
    int i = blockIdx.x * 256 + threadIdx.x;
    if (i >= n4) return;
    float4 v = ((const float4*)in)[i];
    uint32_t h0, l0, h1, l1;
    split2(v.x, v.y, h0, l0);
    split2(v.z, v.w, h1, l1);
    uint2 hh, ll;
    hh.x = h0; hh.y = h1;
    ll.x = l0; ll.y = l1;
    ((uint2*)hi)[i] = hh;
    ((uint2*)lo)[i] = ll;
}

// all 4 weight matrices in one launch (z selects source)
__global__ __launch_bounds__(256) void cvt_hilo_w(
    const float* __restrict__ w0, const float* __restrict__ w1,
    const float* __restrict__ w2, const float* __restrict__ w3,
    __nv_bfloat16* __restrict__ hi, __nv_bfloat16* __restrict__ lo, int n4)
{
    int i = blockIdx.x * 256 + threadIdx.x;
    if (i >= n4) return;
    const int z = blockIdx.z;
    const float* in = (z == 0) ? w0 : ((z == 1) ? w1 : ((z == 2) ? w2 : w3));
    float4 v = ((const float4*)in)[i];
    uint32_t h0, l0, h1, l1;
    split2(v.x, v.y, h0, l0);
    split2(v.z, v.w, h1, l1);
    uint2 hh, ll;
    hh.x = h0; hh.y = h1;
    ll.x = l0; ll.y = l1;
    ((uint2*)(hi + (size_t)z * DD))[i] = hh;
    ((uint2*)(lo + (size_t)z * DD))[i] = ll;
}

// ---------------- bf16x3 GEMM (mma.sync): C[M,N]=(A@W^T+bias)*scale --------
// tile 128x128, KB=32, double-buffered cp.async, 256 threads, 2 CTAs/SM.
// (R7-validated best config; occ 25% — the GEMM is latency-bound at occ 12.5%.)
// Loop order restructured for <=128 live regs: A fragments hoisted per chunk,
// B fragments streamed per-nt (8 live instead of 32).
#define TM 128
#define TN 128
#define KB_F   32
#define NKB_F  (DMODEL / KB_F)         // 32
#define FSTG   (TM * KB_F * 2)         // 8192 B per bf16 submatrix
#define STAGE_F (4 * FSTG)             // 32768
#define GEMM_DSMEM (2 * STAGE_F)       // 65536 -> 2 CTAs/SM fit in 228KB carveout

__device__ __forceinline__ void copy_tiles_f(
    const __nv_bfloat16* __restrict__ Ah, const __nv_bfloat16* __restrict__ Al,
    const __nv_bfloat16* __restrict__ Wh, const __nv_bfloat16* __restrict__ Wl,
    int m0, int n0, int kb, uint32_t base, int tid)
{
    const int koff = kb * KB_F;
#pragma unroll
    for (int i = 0; i < 2; i++) {
        int c   = tid + i * 256;
        int row = c >> 2;
        int c16 = c & 3;
        uint32_t sw = base + swz64(row, c16);
        cp16(sw,            Ah + (size_t)(m0 + row) * DMODEL + koff + c16 * 8);
        cp16(sw + FSTG,     Al + (size_t)(m0 + row) * DMODEL + koff + c16 * 8);
        cp16(sw + 2 * FSTG, Wh + (size_t)(n0 + row) * DMODEL + koff + c16 * 8);
        cp16(sw + 3 * FSTG, Wl + (size_t)(n0 + row) * DMODEL + koff + c16 * 8);
    }
}

__global__ __launch_bounds__(256, 2) void gemm_f(
    const __nv_bfloat16* __restrict__ Ah, const __nv_bfloat16* __restrict__ Al,
    const __nv_bfloat16* __restrict__ Wh0, const __nv_bfloat16* __restrict__ Wl0,
    const float* __restrict__ b0p, const float* __restrict__ b1p,
    const float* __restrict__ b2p,
    __nv_bfloat16* __restrict__ Ch0, __nv_bfloat16* __restrict__ Cl0,
    __nv_bfloat16* __restrict__ Ch1, __nv_bfloat16* __restrict__ Cl1,
    __nv_bfloat16* __restrict__ Ch2, __nv_bfloat16* __restrict__ Cl2,
    float* __restrict__ C, float scale0)
{
    extern __shared__ char dsm[];
    const int tid = threadIdx.x;
    const int wid = tid >> 5;
    const int lid = tid & 31;
    const int m0  = blockIdx.x * TM;
    const int n0  = blockIdx.y * TN;
    const int z   = blockIdx.z;

    const __nv_bfloat16* Wh = Wh0 + (size_t)z * DD;
    const __nv_bfloat16* Wl = Wl0 + (size_t)z * DD;
    const float* bias = (z == 0) ? b0p : ((z == 1) ? b1p : b2p);
    __nv_bfloat16* Ch = (z == 0) ? Ch0 : ((z == 1) ? Ch1 : Ch2);
    __nv_bfloat16* Cl = (z == 0) ? Cl0 : ((z == 1) ? Cl1 : Cl2);
    const float scale = (z == 0) ? scale0 : 1.0f;

    const uint32_t abase = smem_u32(dsm);

    const int wm = wid >> 1;   // 0..3 (32-row strip)
    const int wn = wid & 1;    // 0..1 (64-col strip)

    float acc[2][8][4];
#pragma unroll
    for (int mt = 0; mt < 2; mt++)
#pragma unroll
        for (int nt = 0; nt < 8; nt++)
#pragma unroll
            for (int j = 0; j < 4; j++) acc[mt][nt][j] = 0.0f;

    const int lrow  = (lid & 7) + ((lid >> 3) & 1) * 8;
    const int lhalf = lid >> 4;

    copy_tiles_f(Ah, Al, Wh, Wl, m0, n0, 0, abase, tid);
    CP_COMMIT();

    for (int kb = 0; kb < NKB_F; kb++) {
        const uint32_t sbase = abase + (uint32_t)(kb & 1) * STAGE_F;
        if (kb + 1 < NKB_F) {
            copy_tiles_f(Ah, Al, Wh, Wl, m0, n0, kb + 1,
                         abase + (uint32_t)((kb + 1) & 1) * STAGE_F, tid);
            CP_COMMIT();
            CP_WAIT(1);
        } else {
            CP_WAIT(0);
        }
        __syncthreads();

#pragma unroll
        for (int ks = 0; ks < 2; ks++) {
            const int chunk = ks * 2 + lhalf;
            // hoist A fragments for both 16-row subtiles (32 regs live)
            uint32_t ah[2][4], al[2][4];
#pragma unroll
            for (int mt = 0; mt < 2; mt++) {
                uint32_t aoff = swz64(wm * 32 + mt * 16 + lrow, chunk);
                ldm4(ah[mt], sbase + aoff);
                ldm4(al[mt], sbase + FSTG + aoff);
            }
            // stream B fragments (8 regs live at a time)
#pragma unroll
            for (int nt = 0; nt < 4; nt++) {
                uint32_t boff = swz64(wn * 64 + nt * 16 + lrow, chunk);
                uint32_t bh[4], bl[4];
                ldm4(bh, sbase + 2 * FSTG + boff);
                ldm4(bl, sbase + 3 * FSTG + boff);
#pragma unroll
                for (int mt = 0; mt < 2; mt++) {
                    mma_bf16(acc[mt][2 * nt + 0], ah[mt], bh[0], bh[2]);
                    mma_bf16(acc[mt][2 * nt + 1], ah[mt], bh[1], bh[3]);
                    mma_bf16(acc[mt][2 * nt + 0], ah[mt], bl[0], bl[2]);
                    mma_bf16(acc[mt][2 * nt + 1], ah[mt], bl[1], bl[3]);
                    mma_bf16(acc[mt][2 * nt + 0], al[mt], bh[0], bh[2]);
                    mma_bf16(acc[mt][2 * nt + 1], al[mt], bh[1], bh[3]);
                }
            }
        }
        __syncthreads();
    }

#pragma unroll
    for (int mt = 0; mt < 2; mt++) {
        int r0 = m0 + wm * 32 + mt * 16 + (lid >> 2);
#pragma unroll
        for (int nt = 0; nt < 8; nt++) {
            int c0 = n0 + wn * 64 + nt * 8 + (lid & 3) * 2;
            float bb0 = bias[c0], bb1 = bias[c0 + 1];
            float u0 = (acc[mt][nt][0] + bb0) * scale;
            float u1 = (acc[mt][nt][1] + bb1) * scale;
            float v0 = (acc[mt][nt][2] + bb0) * scale;
            float v1 = (acc[mt][nt][3] + bb1) * scale;
            size_t i0 = (size_t)r0 * DMODEL + c0;
            size_t i1 = (size_t)(r0 + 8) * DMODEL + c0;
            if (Ch) {
                uint32_t h0, l0, h1, l1;
                split2(u0, u1, h0, l0);
                split2(v0, v1, h1, l1);
                *(uint32_t*)(Ch + i0) = h0;
                *(uint32_t*)(Cl + i0) = l0;
                *(uint32_t*)(Ch + i1) = h1;
                *(uint32_t*)(Cl + i1) = l1;
            } else {
                float2 u; u.x = u0; u.y = u1;
                float2 v; v.x = v0; v.y = v1;
                *(float2*)(C + i0) = u;
                *(float2*)(C + i1) = v;
            }
        }
    }
}

// ---------------------------------------------------------------------------
// Tensor-core FlashAttention-2, bf16x3 for both QK^T and PV. exp2-domain
// softmax via single-MUFU ex2.approx (log2(e)/sqrt(d_k) folded into Q).
// CTA = 128 q-rows x one (b,h). 8 warps x 16 q-rows. Key tiles of 64.
// ---------------------------------------------------------------------------
#define AT_STG   33792
#define AT_KVOFF 32768
#define AT_DSMEM (AT_KVOFF + 2 * AT_STG)     // 100352

__global__ __launch_bounds__(256, 1) void attn_tc(
    const __nv_bfloat16* __restrict__ Qh_, const __nv_bfloat16* __restrict__ Ql_,
    const __nv_bfloat16* __restrict__ Kh_, const __nv_bfloat16* __restrict__ Kl_,
    const __nv_bfloat16* __restrict__ Vh_, const __nv_bfloat16* __restrict__ Vl_,
    const int* __restrict__ mask,
    __nv_bfloat16* __restrict__ Oh_, __nv_bfloat16* __restrict__ Ol_)
{
    extern __shared__ char sm[];
    const uint32_t sb = smem_u32(sm);

    const int tid = threadIdx.x;
    const int w   = tid >> 5;
    const int l   = tid & 31;
    const int bh  = blockIdx.y;
    const int b   = bh >> 4;
    const int h   = bh & 15;
    const int q0  = blockIdx.x * 128;

    const size_t rowQ  = ((size_t)(b * SEQ + q0)) * DMODEL + h * DKH;
    const size_t rowK0 = ((size_t)(b * SEQ)) * DMODEL + h * DKH;
    const int*   mg    = mask + b * SEQ;

    // --- Q tiles (hi/lo) -> smem, group 0 ---
#pragma unroll
    for (int i = 0; i < 4; i++) {
        int c   = tid + i * 256;
        int row = c >> 3;
        int c8  = c & 7;
        uint32_t sw = SWZ128(row * 128 + c8 * 16);
        cp16(sb + sw,         Qh_ + rowQ + (size_t)row * DMODEL + c8 * 8);
        cp16(sb + 16384 + sw, Ql_ + rowQ + (size_t)row * DMODEL + c8 * 8);
    }
    CP_COMMIT();

#define AT_COPY_KV(kb_, s_) do {                                                 \
    uint32_t kvb_ = sb + AT_KVOFF + (uint32_t)(s_) * AT_STG;                     \
    {                                                                            \
        int c_   = tid;                                                          \
        int row_ = c_ >> 3;                                                      \
        int c8_  = c_ & 7;                                                       \
        uint32_t sw_ = SWZ128(row_ * 128 + c8_ * 16);                            \
        size_t g_ = rowK0 + (size_t)((kb_) * 64 + row_) * DMODEL + c8_ * 8;      \
        cp16(kvb_ + sw_,         Kh_ + g_);                                      \
        cp16(kvb_ + 8192 + sw_,  Kl_ + g_);                                      \
        cp16(kvb_ + 16384 + sw_, Vh_ + g_);                                      \
        cp16(kvb_ + 24576 + sw_, Vl_ + g_);                                      \
    }                                                                            \
    {                                                                            \
        int c_   = tid + 256;                                                    \
        int row_ = c_ >> 3;                                                      \
        int c8_  = c_ & 7;                                                       \
        uint32_t sw_ = SWZ128(row_ * 128 + c8_ * 16);                            \
        size_t g_ = rowK0 + (size_t)((kb_) * 64 + row_) * DMODEL + c8_ * 8;      \
        cp16(kvb_ + sw_,         Kh_ + g_);                                      \
        cp16(kvb_ + 8192 + sw_,  Kl_ + g_);                                      \
        cp16(kvb_ + 16384 + sw_, Vh_ + g_);                                      \
        cp16(kvb_ + 24576 + sw_, Vl_ + g_);                                      \
    }                                                                            \
    if (tid < 16) cp16(kvb_ + 32768 + tid * 16, mg + (kb_) * 64 + tid * 4);      \
} while (0)

    AT_COPY_KV(0, 0);
    CP_COMMIT();

    CP_WAIT(1);
    __syncthreads();

    // --- preload Q fragments (held across the whole loop) ---
    const int lrow = (l & 7) + ((l >> 3) & 1) * 8;
    const int lkb  = (l >> 4) * 16;
    uint32_t qh[4][4], ql[4][4];
#pragma unroll
    for (int kt = 0; kt < 4; kt++) {
        uint32_t qa = sb + SWZ128((w * 16 + lrow) * 128 + kt * 32 + lkb);
        ldm4(qh[kt], qa);
        ldm4(ql[kt], qa + 16384);
    }

    float O[8][4];
    float S[8][4];
    float m0r = -INFINITY, m1r = -INFINITY, l0r = 0.0f, l1r = 0.0f;
#pragma unroll
    for (int nt = 0; nt < 8; nt++)
#pragma unroll
        for (int j = 0; j < 4; j++) O[nt][j] = 0.0f;

    for (int kb = 0; kb < SEQ / 64; kb++) {
        const int s = kb & 1;
        if (kb + 1 < SEQ / 64) {
            AT_COPY_KV(kb + 1, s ^ 1);
            CP_COMMIT();
            CP_WAIT(1);
        } else {
            CP_WAIT(0);
        }
        __syncthreads();

        const uint32_t kvb = sb + AT_KVOFF + (uint32_t)s * AT_STG;
        const char* kvc = sm + AT_KVOFF + (size_t)s * AT_STG;

        // ---- S = Q @ K^T (bf16x3), log2 domain ----
#pragma unroll
        for (int nt = 0; nt < 8; nt++)
#pragma unroll
            for (int j = 0; j < 4; j++) S[nt][j] = 0.0f;

#pragma unroll
        for (int kt = 0; kt < 4; kt++) {
#pragma unroll
            for (int np = 0; np < 4; np++) {
                uint32_t ka = kvb + SWZ128((np * 16 + lrow) * 128 + kt * 32 + lkb);
                uint32_t kh[4], kl[4];
                ldm4(kh, ka);
                ldm4(kl, ka + 8192);
                mma_bf16(S[2 * np + 0], qh[kt], kh[0], kh[2]);
                mma_bf16(S[2 * np + 0], qh[kt], kl[0], kl[2]);
                mma_bf16(S[2 * np + 0], ql[kt], kh[0], kh[2]);
                mma_bf16(S[2 * np + 1], qh[kt], kh[1], kh[3]);
                mma_bf16(S[2 * np + 1], qh[kt], kl[1], kl[3]);
                mma_bf16(S[2 * np + 1], ql[kt], kh[1], kh[3]);
            }
        }

        // ---- mask + online softmax (base-2, single-MUFU ex2) ----
        const int* smask = (const int*)(kvc + 32768);
        float mx0 = -INFINITY, mx1 = -INFINITY;
#pragma unroll
        for (int nt = 0; nt < 8; nt++) {
            int2 mk = *(const int2*)(smask + nt * 8 + (l & 3) * 2);
            if (mk.x == 0) { S[nt][0] = -1e9f; S[nt][2] = -1e9f; }
            if (mk.y == 0) { S[nt][1] = -1e9f; S[nt][3] = -1e9f; }
            mx0 = fmaxf(mx0, fmaxf(S[nt][0], S[nt][1]));
            mx1 = fmaxf(mx1, fmaxf(S[nt][2], S[nt][3]));
        }
        mx0 = fmaxf(mx0, __shfl_xor_sync(0xffffffffu, mx0, 1));
        mx0 = fmaxf(mx0, __shfl_xor_sync(0xffffffffu, mx0, 2));
        mx1 = fmaxf(mx1, __shfl_xor_sync(0xffffffffu, mx1, 1));
        mx1 = fmaxf(mx1, __shfl_xor_sync(0xffffffffu, mx1, 2));

        float mn0 = fmaxf(m0r, mx0);
        float mn1 = fmaxf(m1r, mx1);
        float a0 = fexp2(m0r - mn0);
        float a1 = fexp2(m1r - mn1);
        m0r = mn0; m1r = mn1;

        float sum0 = 0.0f, sum1 = 0.0f;
#pragma unroll
        for (int nt = 0; nt < 8; nt++) {
            S[nt][0] = fexp2(S[nt][0] - mn0);
            S[nt][1] = fexp2(S[nt][1] - mn0);
            S[nt][2] = fexp2(S[nt][2] - mn1);
            S[nt][3] = fexp2(S[nt][3] - mn1);
            sum0 += S[nt][0] + S[nt][1];
            sum1 += S[nt][2] + S[nt][3];
        }
        sum0 += __shfl_xor_sync(0xffffffffu, sum0, 1);
        sum0 += __shfl_xor_sync(0xffffffffu, sum0, 2);
        sum1 += __shfl_xor_sync(0xffffffffu, sum1, 1);
        sum1 += __shfl_xor_sync(0xffffffffu, sum1, 2);
        l0r = l0r * a0 + sum0;
        l1r = l1r * a1 + sum1;

#pragma unroll
        for (int nt = 0; nt < 8; nt++) {
            O[nt][0] *= a0; O[nt][1] *= a0;
            O[nt][2] *= a1; O[nt][3] *= a1;
        }

        // ---- O += P @ V (bf16x3) ----
#pragma unroll
        for (int kt = 0; kt < 4; kt++) {
            uint32_t ph[4], pl[4];
            split2(S[2 * kt + 0][0], S[2 * kt + 0][1], ph[0], pl[0]);
            split2(S[2 * kt + 0][2], S[2 * kt + 0][3], ph[1], pl[1]);
            split2(S[2 * kt + 1][0], S[2 * kt + 1][1], ph[2], pl[2]);
            split2(S[2 * kt + 1][2], S[2 * kt + 1][3], ph[3], pl[3]);
#pragma unroll
            for (int dp = 0; dp < 4; dp++) {
                uint32_t va = kvb + 16384 + SWZ128((kt * 16 + lrow) * 128 + dp * 32 + lkb);
                uint32_t vh[4], vl[4];
                ldm4t(vh, va);
                ldm4t(vl, va + 8192);
                mma_bf16(O[2 * dp + 0], ph, vh[0], vh[1]);
                mma_bf16(O[2 * dp + 0], ph, vl[0], vl[1]);
                mma_bf16(O[2 * dp + 0], pl, vh[0], vh[1]);
                mma_bf16(O[2 * dp + 1], ph, vh[2], vh[3]);
                mma_bf16(O[2 * dp + 1], ph, vl[2], vl[3]);
                mma_bf16(O[2 * dp + 1], pl, vh[2], vh[3]);
            }
        }
        __syncthreads();
    }

    // ---- epilogue: normalize, split hi/lo, store ----
    float inv0 = 1.0f / l0r;
    float inv1 = 1.0f / l1r;
    const int r0 = b * SEQ + q0 + w * 16 + (l >> 2);
#pragma unroll
    for (int nt = 0; nt < 8; nt++) {
        size_t idx = (size_t)r0 * DMODEL + h * DKH + nt * 8 + (l & 3) * 2;
        uint32_t hA, lA, hB, lB;
        split2(O[nt][0] * inv0, O[nt][1] * inv0, hA, lA);
        split2(O[nt][2] * inv1, O[nt][3] * inv1, hB, lB);
        *(uint32_t*)(Oh_ + idx)              = hA;
        *(uint32_t*)(Ol_ + idx)              = lA;
        *(uint32_t*)(Oh_ + idx + 8 * DMODEL) = hB;
        *(uint32_t*)(Ol_ + idx + 8 * DMODEL) = lB;
    }
#undef AT_COPY_KV
}

// ---------------------------------------------------------------------------
extern "C" void kernel_launch(void* const* d_in, const int* in_sizes, int n_in,
                              void* d_out, int out_size)
{
    const float* x    = (const float*)d_in[0];
    const int*   mask = (const int*)  d_in[1];
    const float* Wq   = (const float*)d_in[2];
    const float* bq   = (const float*)d_in[3];
    const float* Wk   = (const float*)d_in[4];
    const float* bk   = (const float*)d_in[5];
    const float* Wv   = (const float*)d_in[6];
    const float* bv   = (const float*)d_in[7];
    const float* Wo   = (const float*)d_in[8];
    const float* bo   = (const float*)d_in[9];
    float* out = (float*)d_out;

    __nv_bfloat16 *xh, *xl, *wh, *wl, *qh, *ql, *kh, *kl, *vh, *vl, *ah, *al;
    cudaGetSymbolAddress((void**)&xh, g_xh);
    cudaGetSymbolAddress((void**)&xl, g_xl);
    cudaGetSymbolAddress((void**)&wh, g_wh);
    cudaGetSymbolAddress((void**)&wl, g_wl);
    cudaGetSymbolAddress((void**)&qh, g_qh);
    cudaGetSymbolAddress((void**)&ql, g_ql);
    cudaGetSymbolAddress((void**)&kh, g_kh);
    cudaGetSymbolAddress((void**)&kl, g_kl);
    cudaGetSymbolAddress((void**)&vh, g_vh);
    cudaGetSymbolAddress((void**)&vl, g_vl);
    cudaGetSymbolAddress((void**)&ah, g_ah);
    cudaGetSymbolAddress((void**)&al, g_al);

    cudaFuncSetAttribute(gemm_f,
                         cudaFuncAttributeMaxDynamicSharedMemorySize, GEMM_DSMEM);
    cudaFuncSetAttribute(attn_tc,
                         cudaFuncAttributeMaxDynamicSharedMemorySize, AT_DSMEM);

    const int n4x = MR * DMODEL / 4;
    const int n4w = DD / 4;

    cvt_hilo<<<n4x / 256, 256>>>(x, xh, xl, n4x);
    dim3 gw(n4w / 256, 1, 4);
    cvt_hilo_w<<<gw, 256>>>(Wq, Wk, Wv, Wo, wh, wl, n4w);

    // merged QKV projection: z = 0/1/2 -> Q/K/V. Q gets log2e/sqrt(dk) scale.
    dim3 gqkv(MR / TM, DMODEL / TN, 3);   // 64 x 8 x 3
    gemm_f<<<gqkv, 256, GEMM_DSMEM>>>(xh, xl, wh, wl, bq, bk, bv,
                                      qh, ql, kh, kl, vh, vl,
                                      nullptr, QSCALE);

    dim3 ga(SEQ / 128, BATCH * NHEADS);   // 16 x 64
    attn_tc<<<ga, 256, AT_DSMEM>>>(qh, ql, kh, kl, vh, vl, mask, ah, al);

    // output projection (z extent 1, fp32 output)
    dim3 go(MR / TM, DMODEL / TN, 1);
    gemm_f<<<go, 256, GEMM_DSMEM>>>(ah, al, wh + 3 * (size_t)DD, wl + 3 * (size_t)DD,
                                    bo, bo, bo,
                                    nullptr, nullptr, nullptr, nullptr, nullptr, nullptr,
                                    out, 1.0f);
}

// round 13
// speedup vs baseline: 1.4282x; 1.4282x over previous
#include <cuda_runtime.h>
#include <cuda_bf16.h>
#include <math.h>
#include <stdint.h>

#define DMODEL 1024
#define NHEADS 16
#define DKH    64
#define BATCH  4
#define SEQ    2048
#define MR     (BATCH * SEQ)   // 8192 rows
#define DD     (DMODEL * DMODEL)

// ---------------- scratch (allocation-free rule: __device__ globals) -------
static __device__ __nv_bfloat16 g_xh[(size_t)MR * DMODEL];
static __device__ __nv_bfloat16 g_xl[(size_t)MR * DMODEL];
static __device__ __nv_bfloat16 g_wh[(size_t)4 * DD];
static __device__ __nv_bfloat16 g_wl[(size_t)4 * DD];
static __device__ __nv_bfloat16 g_qh[(size_t)MR * DMODEL];
static __device__ __nv_bfloat16 g_ql[(size_t)MR * DMODEL];
static __device__ __nv_bfloat16 g_kh[(size_t)MR * DMODEL];
static __device__ __nv_bfloat16 g_kl[(size_t)MR * DMODEL];
static __device__ __nv_bfloat16 g_vh[(size_t)MR * DMODEL];
static __device__ __nv_bfloat16 g_vl[(size_t)MR * DMODEL];
static __device__ __nv_bfloat16 g_ah[(size_t)MR * DMODEL];
static __device__ __nv_bfloat16 g_al[(size_t)MR * DMODEL];

// ---------------- PTX helpers (baseline, legal on compute_103) -------------
__device__ __forceinline__ uint32_t smem_u32(const void* p) {
    uint32_t a;
    asm("{ .reg .u64 t; cvta.to.shared.u64 t, %1; cvt.u32.u64 %0, t; }"
        : "=r"(a) : "l"(p));
    return a;
}

__device__ __forceinline__ void cp16(uint32_t dst, const void* src) {
    asm volatile("cp.async.cg.shared.global [%0], [%1], 16;\n"
                 :: "r"(dst), "l"(src) : "memory");
}
#define CP_COMMIT() asm volatile("cp.async.commit_group;\n" ::: "memory")
#define CP_WAIT(n)  asm volatile("cp.async.wait_group %0;\n" :: "n"(n) : "memory")

__device__ __forceinline__ void ldm4(uint32_t* r, uint32_t addr) {
    asm volatile("ldmatrix.sync.aligned.m8n8.x4.shared.b16 {%0,%1,%2,%3}, [%4];"
                 : "=r"(r[0]), "=r"(r[1]), "=r"(r[2]), "=r"(r[3]) : "r"(addr));
}

__device__ __forceinline__ void ldm4t(uint32_t* r, uint32_t addr) {
    asm volatile("ldmatrix.sync.aligned.m8n8.x4.trans.shared.b16 {%0,%1,%2,%3}, [%4];"
                 : "=r"(r[0]), "=r"(r[1]), "=r"(r[2]), "=r"(r[3]) : "r"(addr));
}

__device__ __forceinline__ void mma_bf16(float* c, const uint32_t* a,
                                         uint32_t b0, uint32_t b1) {
    asm volatile(
        "mma.sync.aligned.m16n8k16.row.col.f32.bf16.bf16.f32 "
        "{%0,%1,%2,%3}, {%4,%5,%6,%7}, {%8,%9}, {%0,%1,%2,%3};"
        : "+f"(c[0]), "+f"(c[1]), "+f"(c[2]), "+f"(c[3])
        : "r"(a[0]), "r"(a[1]), "r"(a[2]), "r"(a[3]), "r"(b0), "r"(b1));
}

// split fp32 pair into packed bf16 hi (truncated) + bf16 lo (rn of residual)
__device__ __forceinline__ void split2(float v0, float v1, uint32_t& h, uint32_t& l) {
    uint32_t b0 = __float_as_uint(v0), b1 = __float_as_uint(v1);
    h = __byte_perm(b0, b1, 0x7632);
    float r0 = v0 - __uint_as_float(b0 & 0xFFFF0000u);
    float r1 = v1 - __uint_as_float(b1 & 0xFFFF0000u);
    asm("cvt.rn.bf16x2.f32 %0, %1, %2;" : "=r"(l) : "f"(r1), "f"(r0));
}

// pack fp32 pair to bf16x2 (round-to-nearest, no residual)
__device__ __forceinline__ uint32_t pack2(float v0, float v1) {
    uint32_t r;
    asm("cvt.rn.bf16x2.f32 %0, %1, %2;" : "=r"(r) : "f"(v1), "f"(v0));
    return r;
}

// SW128 swizzle for 128B rows
#define SWZ128(o) ((o) ^ (((o) >> 3) & 0x70))
// swizzle for 64B rows
__device__ __forceinline__ uint32_t swz64(int row, int c16) {
    return (uint32_t)(row * 64 + ((c16 ^ ((row >> 1) & 3)) << 4));
}

// ---------------- fp32 -> (bf16 hi, bf16 lo) conversion --------------------
__global__ __launch_bounds__(256) void cvt_hilo(
    const float* __restrict__ in,
    __nv_bfloat16* __restrict__ hi, __nv_bfloat16* __restrict__ lo, int n4)
{
    int i = blockIdx.x * 256 + threadIdx.x;
    if (i >= n4) return;
    float4 v = ((const float4*)in)[i];
    uint32_t h0, l0, h1, l1;
    split2(v.x, v.y, h0, l0);
    split2(v.z, v.w, h1, l1);
    uint2 hh, ll;
    hh.x = h0; hh.y = h1;
    ll.x = l0; ll.y = l1;
    ((uint2*)hi)[i] = hh;
    ((uint2*)lo)[i] = ll;
}

// all 4 weight matrices in one launch (z selects source)
__global__ __launch_bounds__(256) void cvt_hilo_w(
    const float* __restrict__ w0, const float* __restrict__ w1,
    const float* __restrict__ w2, const float* __restrict__ w3,
    __nv_bfloat16* __restrict__ hi, __nv_bfloat16* __restrict__ lo, int n4)
{
    int i = blockIdx.x * 256 + threadIdx.x;
    if (i >= n4) return;
    const int z = blockIdx.z;
    const float* in = (z == 0) ? w0 : ((z == 1) ? w1 : ((z == 2) ? w2 : w3));
    float4 v = ((const float4*)in)[i];
    uint32_t h0, l0, h1, l1;
    split2(v.x, v.y, h0, l0);
    split2(v.z, v.w, h1, l1);
    uint2 hh, ll;
    hh.x = h0; hh.y = h1;
    ll.x = l0; ll.y = l1;
    ((uint2*)(hi + (size_t)z * DD))[i] = hh;
    ((uint2*)(lo + (size_t)z * DD))[i] = ll;
}

// ---------------- bf16x3 GEMM (mma.sync): C[M,N]=(A@W^T+bias)*scale --------
// tile 128x128, KB=32, double-buffered cp.async, 256 threads.
// Exact R6 (measured-best) configuration: 132 KB dsmem request, (256,1).
#define TM 128
#define TN 128
#define KB_F   32
#define NKB_F  (DMODEL / KB_F)         // 32
#define FSTG   (TM * KB_F * 2)         // 8192 B per bf16 submatrix
#define STAGE_F (4 * FSTG)             // 32768
#define GEMM_DSMEM 132096              // R6's request (2*65536+1024)

__device__ __forceinline__ void copy_tiles_f(
    const __nv_bfloat16* __restrict__ Ah, const __nv_bfloat16* __restrict__ Al,
    const __nv_bfloat16* __restrict__ Wh, const __nv_bfloat16* __restrict__ Wl,
    int m0, int n0, int kb, uint32_t base, int tid)
{
    const int koff = kb * KB_F;
#pragma unroll
    for (int i = 0; i < 2; i++) {
        int c   = tid + i * 256;
        int row = c >> 2;
        int c16 = c & 3;
        uint32_t sw = base + swz64(row, c16);
        cp16(sw,            Ah + (size_t)(m0 + row) * DMODEL + koff + c16 * 8);
        cp16(sw + FSTG,     Al + (size_t)(m0 + row) * DMODEL + koff + c16 * 8);
        cp16(sw + 2 * FSTG, Wh + (size_t)(n0 + row) * DMODEL + koff + c16 * 8);
        cp16(sw + 3 * FSTG, Wl + (size_t)(n0 + row) * DMODEL + koff + c16 * 8);
    }
}

__global__ __launch_bounds__(256, 1) void gemm_tc(
    const __nv_bfloat16* __restrict__ Ah, const __nv_bfloat16* __restrict__ Al,
    const __nv_bfloat16* __restrict__ Wh, const __nv_bfloat16* __restrict__ Wl,
    const float* __restrict__ bias, float* __restrict__ C,
    __nv_bfloat16* __restrict__ Ch, __nv_bfloat16* __restrict__ Cl, float scale)
{
    extern __shared__ char dsm[];
    const int tid = threadIdx.x;
    const int wid = tid >> 5;
    const int lid = tid & 31;
    const int m0  = blockIdx.x * TM;
    const int n0  = blockIdx.y * TN;

    uint32_t draw  = smem_u32(dsm);
    uint32_t abase = (draw + 1023) & ~1023u;

    const int wm = wid >> 1;   // 0..3 (32-row strip)
    const int wn = wid & 1;    // 0..1 (64-col strip)

    float acc[2][8][4];
#pragma unroll
    for (int mt = 0; mt < 2; mt++)
#pragma unroll
        for (int nt = 0; nt < 8; nt++)
#pragma unroll
            for (int j = 0; j < 4; j++) acc[mt][nt][j] = 0.0f;

    const int lrow  = (lid & 7) + ((lid >> 3) & 1) * 8;
    const int lhalf = lid >> 4;

    copy_tiles_f(Ah, Al, Wh, Wl, m0, n0, 0, abase, tid);
    CP_COMMIT();

    for (int kb = 0; kb < NKB_F; kb++) {
        const uint32_t sbase = abase + (uint32_t)(kb & 1) * STAGE_F;
        if (kb + 1 < NKB_F) {
            copy_tiles_f(Ah, Al, Wh, Wl, m0, n0, kb + 1,
                         abase + (uint32_t)((kb + 1) & 1) * STAGE_F, tid);
            CP_COMMIT();
            CP_WAIT(1);
        } else {
            CP_WAIT(0);
        }
        __syncthreads();

#pragma unroll
        for (int ks = 0; ks < 2; ks++) {
            const int chunk = ks * 2 + lhalf;
            uint32_t bh[4][4], bl[4][4];
#pragma unroll
            for (int nt = 0; nt < 4; nt++) {
                int brow = wn * 64 + nt * 16 + lrow;
                uint32_t boff = swz64(brow, chunk);
                ldm4(bh[nt], sbase + 2 * FSTG + boff);
                ldm4(bl[nt], sbase + 3 * FSTG + boff);
            }
#pragma unroll
            for (int mt = 0; mt < 2; mt++) {
                int arow = wm * 32 + mt * 16 + lrow;
                uint32_t aoff = swz64(arow, chunk);
                uint32_t ah[4], al[4];
                ldm4(ah, sbase + aoff);
                ldm4(al, sbase + FSTG + aoff);
#pragma unroll
                for (int nt = 0; nt < 4; nt++) {
                    mma_bf16(acc[mt][2 * nt + 0], ah, bh[nt][0], bh[nt][2]);
                    mma_bf16(acc[mt][2 * nt + 1], ah, bh[nt][1], bh[nt][3]);
                    mma_bf16(acc[mt][2 * nt + 0], ah, bl[nt][0], bl[nt][2]);
                    mma_bf16(acc[mt][2 * nt + 1], ah, bl[nt][1], bl[nt][3]);
                    mma_bf16(acc[mt][2 * nt + 0], al, bh[nt][0], bh[nt][2]);
                    mma_bf16(acc[mt][2 * nt + 1], al, bh[nt][1], bh[nt][3]);
                }
            }
        }
        __syncthreads();
    }

#pragma unroll
    for (int mt = 0; mt < 2; mt++) {
        int r0 = m0 + wm * 32 + mt * 16 + (lid >> 2);
#pragma unroll
        for (int nt = 0; nt < 8; nt++) {
            int c0 = n0 + wn * 64 + nt * 8 + (lid & 3) * 2;
            float bb0 = bias[c0], bb1 = bias[c0 + 1];
            float u0 = (acc[mt][nt][0] + bb0) * scale;
            float u1 = (acc[mt][nt][1] + bb1) * scale;
            float v0 = (acc[mt][nt][2] + bb0) * scale;
            float v1 = (acc[mt][nt][3] + bb1) * scale;
            size_t i0 = (size_t)r0 * DMODEL + c0;
            size_t i1 = (size_t)(r0 + 8) * DMODEL + c0;
            if (Ch) {
                uint32_t h0, l0, h1, l1;
                split2(u0, u1, h0, l0);
                split2(v0, v1, h1, l1);
                *(uint32_t*)(Ch + i0) = h0;
                *(uint32_t*)(Cl + i0) = l0;
                *(uint32_t*)(Ch + i1) = h1;
                *(uint32_t*)(Cl + i1) = l1;
            } else {
                float2 u; u.x = u0; u.y = u1;
                float2 v; v.x = v0; v.y = v1;
                *(float2*)(C + i0) = u;
                *(float2*)(C + i1) = v;
            }
        }
    }
}

// ---------------------------------------------------------------------------
// Tensor-core FlashAttention-2. QK^T: bf16x3 (full precision). PV: 2-pass
// (ph*vh + ph*vl) — P's bf16 residual dropped; softmax probs are in [0,1]
// and the dropped term is <= 2^-9 relative with sign-random accumulation.
// __expf softmax, 1/sqrt(d_k) folded into Q (R6-validated).
// CTA = 128 q-rows x one (b,h). 8 warps x 16 q-rows. Key tiles of 64.
// ---------------------------------------------------------------------------
#define AT_STG   33792
#define AT_KVOFF 32768
#define AT_DSMEM (AT_KVOFF + 2 * AT_STG)     // 100352

__global__ __launch_bounds__(256, 1) void attn_tc(
    const __nv_bfloat16* __restrict__ Qh_, const __nv_bfloat16* __restrict__ Ql_,
    const __nv_bfloat16* __restrict__ Kh_, const __nv_bfloat16* __restrict__ Kl_,
    const __nv_bfloat16* __restrict__ Vh_, const __nv_bfloat16* __restrict__ Vl_,
    const int* __restrict__ mask,
    __nv_bfloat16* __restrict__ Oh_, __nv_bfloat16* __restrict__ Ol_)
{
    extern __shared__ char sm[];
    const uint32_t sb = smem_u32(sm);

    const int tid = threadIdx.x;
    const int w   = tid >> 5;
    const int l   = tid & 31;
    const int bh  = blockIdx.y;
    const int b   = bh >> 4;
    const int h   = bh & 15;
    const int q0  = blockIdx.x * 128;

    const size_t rowQ  = ((size_t)(b * SEQ + q0)) * DMODEL + h * DKH;
    const size_t rowK0 = ((size_t)(b * SEQ)) * DMODEL + h * DKH;
    const int*   mg    = mask + b * SEQ;

    // --- Q tiles (hi/lo) -> smem, group 0 ---
#pragma unroll
    for (int i = 0; i < 4; i++) {
        int c   = tid + i * 256;
        int row = c >> 3;
        int c8  = c & 7;
        uint32_t sw = SWZ128(row * 128 + c8 * 16);
        cp16(sb + sw,         Qh_ + rowQ + (size_t)row * DMODEL + c8 * 8);
        cp16(sb + 16384 + sw, Ql_ + rowQ + (size_t)row * DMODEL + c8 * 8);
    }
    CP_COMMIT();

#define AT_COPY_KV(kb_, s_) do {                                                 \
    uint32_t kvb_ = sb + AT_KVOFF + (uint32_t)(s_) * AT_STG;                     \
    {                                                                            \
        int c_   = tid;                                                          \
        int row_ = c_ >> 3;                                                      \
        int c8_  = c_ & 7;                                                       \
        uint32_t sw_ = SWZ128(row_ * 128 + c8_ * 16);                            \
        size_t g_ = rowK0 + (size_t)((kb_) * 64 + row_) * DMODEL + c8_ * 8;      \
        cp16(kvb_ + sw_,         Kh_ + g_);                                      \
        cp16(kvb_ + 8192 + sw_,  Kl_ + g_);                                      \
        cp16(kvb_ + 16384 + sw_, Vh_ + g_);                                      \
        cp16(kvb_ + 24576 + sw_, Vl_ + g_);                                      \
    }                                                                            \
    {                                                                            \
        int c_   = tid + 256;                                                    \
        int row_ = c_ >> 3;                                                      \
        int c8_  = c_ & 7;                                                       \
        uint32_t sw_ = SWZ128(row_ * 128 + c8_ * 16);                            \
        size_t g_ = rowK0 + (size_t)((kb_) * 64 + row_) * DMODEL + c8_ * 8;      \
        cp16(kvb_ + sw_,         Kh_ + g_);                                      \
        cp16(kvb_ + 8192 + sw_,  Kl_ + g_);                                      \
        cp16(kvb_ + 16384 + sw_, Vh_ + g_);                                      \
        cp16(kvb_ + 24576 + sw_, Vl_ + g_);                                      \
    }                                                                            \
    if (tid < 16) cp16(kvb_ + 32768 + tid * 16, mg + (kb_) * 64 + tid * 4);      \
} while (0)

    AT_COPY_KV(0, 0);
    CP_COMMIT();

    CP_WAIT(1);
    __syncthreads();

    // --- preload Q fragments (held across the whole loop) ---
    const int lrow = (l & 7) + ((l >> 3) & 1) * 8;
    const int lkb  = (l >> 4) * 16;
    uint32_t qh[4][4], ql[4][4];
#pragma unroll
    for (int kt = 0; kt < 4; kt++) {
        uint32_t qa = sb + SWZ128((w * 16 + lrow) * 128 + kt * 32 + lkb);
        ldm4(qh[kt], qa);
        ldm4(ql[kt], qa + 16384);
    }

    float O[8][4];
    float S[8][4];
    float m0r = -INFINITY, m1r = -INFINITY, l0r = 0.0f, l1r = 0.0f;
#pragma unroll
    for (int nt = 0; nt < 8; nt++)
#pragma unroll
        for (int j = 0; j < 4; j++) O[nt][j] = 0.0f;

    for (int kb = 0; kb < SEQ / 64; kb++) {
        const int s = kb & 1;
        if (kb + 1 < SEQ / 64) {
            AT_COPY_KV(kb + 1, s ^ 1);
            CP_COMMIT();
            CP_WAIT(1);
        } else {
            CP_WAIT(0);
        }
        __syncthreads();

        const uint32_t kvb = sb + AT_KVOFF + (uint32_t)s * AT_STG;
        const char* kvc = sm + AT_KVOFF + (size_t)s * AT_STG;

        // ---- S = Q @ K^T (bf16x3) ----
#pragma unroll
        for (int nt = 0; nt < 8; nt++)
#pragma unroll
            for (int j = 0; j < 4; j++) S[nt][j] = 0.0f;

#pragma unroll
        for (int kt = 0; kt < 4; kt++) {
#pragma unroll
            for (int np = 0; np < 4; np++) {
                uint32_t ka = kvb + SWZ128((np * 16 + lrow) * 128 + kt * 32 + lkb);
                uint32_t kh[4], kl[4];
                ldm4(kh, ka);
                ldm4(kl, ka + 8192);
                mma_bf16(S[2 * np + 0], qh[kt], kh[0], kh[2]);
                mma_bf16(S[2 * np + 0], qh[kt], kl[0], kl[2]);
                mma_bf16(S[2 * np + 0], ql[kt], kh[0], kh[2]);
                mma_bf16(S[2 * np + 1], qh[kt], kh[1], kh[3]);
                mma_bf16(S[2 * np + 1], qh[kt], kl[1], kl[3]);
                mma_bf16(S[2 * np + 1], ql[kt], kh[1], kh[3]);
            }
        }

        // ---- mask + online softmax ----
        const int* smask = (const int*)(kvc + 32768);
        float mx0 = -INFINITY, mx1 = -INFINITY;
#pragma unroll
        for (int nt = 0; nt < 8; nt++) {
            int2 mk = *(const int2*)(smask + nt * 8 + (l & 3) * 2);
            if (mk.x == 0) { S[nt][0] = -1e9f; S[nt][2] = -1e9f; }
            if (mk.y == 0) { S[nt][1] = -1e9f; S[nt][3] = -1e9f; }
            mx0 = fmaxf(mx0, fmaxf(S[nt][0], S[nt][1]));
            mx1 = fmaxf(mx1, fmaxf(S[nt][2], S[nt][3]));
        }
        mx0 = fmaxf(mx0, __shfl_xor_sync(0xffffffffu, mx0, 1));
        mx0 = fmaxf(mx0, __shfl_xor_sync(0xffffffffu, mx0, 2));
        mx1 = fmaxf(mx1, __shfl_xor_sync(0xffffffffu, mx1, 1));
        mx1 = fmaxf(mx1, __shfl_xor_sync(0xffffffffu, mx1, 2));

        float mn0 = fmaxf(m0r, mx0);
        float mn1 = fmaxf(m1r, mx1);
        float a0 = __expf(m0r - mn0);
        float a1 = __expf(m1r - mn1);
        m0r = mn0; m1r = mn1;

        float sum0 = 0.0f, sum1 = 0.0f;
#pragma unroll
        for (int nt = 0; nt < 8; nt++) {
            S[nt][0] = __expf(S[nt][0] - mn0);
            S[nt][1] = __expf(S[nt][1] - mn0);
            S[nt][2] = __expf(S[nt][2] - mn1);
            S[nt][3] = __expf(S[nt][3] - mn1);
            sum0 += S[nt][0] + S[nt][1];
            sum1 += S[nt][2] + S[nt][3];
        }
        sum0 += __shfl_xor_sync(0xffffffffu, sum0, 1);
        sum0 += __shfl_xor_sync(0xffffffffu, sum0, 2);
        sum1 += __shfl_xor_sync(0xffffffffu, sum1, 1);
        sum1 += __shfl_xor_sync(0xffffffffu, sum1, 2);
        l0r = l0r * a0 + sum0;
        l1r = l1r * a1 + sum1;

#pragma unroll
        for (int nt = 0; nt < 8; nt++) {
            O[nt][0] *= a0; O[nt][1] *= a0;
            O[nt][2] *= a1; O[nt][3] *= a1;
        }

        // ---- O += P @ V (2-pass: ph*vh + ph*vl; pl dropped) ----
#pragma unroll
        for (int kt = 0; kt < 4; kt++) {
            uint32_t ph[4];
            ph[0] = pack2(S[2 * kt + 0][0], S[2 * kt + 0][1]);
            ph[1] = pack2(S[2 * kt + 0][2], S[2 * kt + 0][3]);
            ph[2] = pack2(S[2 * kt + 1][0], S[2 * kt + 1][1]);
            ph[3] = pack2(S[2 * kt + 1][2], S[2 * kt + 1][3]);
#pragma unroll
            for (int dp = 0; dp < 4; dp++) {
                uint32_t va = kvb + 16384 + SWZ128((kt * 16 + lrow) * 128 + dp * 32 + lkb);
                uint32_t vh[4], vl[4];
                ldm4t(vh, va);
                ldm4t(vl, va + 8192);
                mma_bf16(O[2 * dp + 0], ph, vh[0], vh[1]);
                mma_bf16(O[2 * dp + 0], ph, vl[0], vl[1]);
                mma_bf16(O[2 * dp + 1], ph, vh[2], vh[3]);
                mma_bf16(O[2 * dp + 1], ph, vl[2], vl[3]);
            }
        }
        __syncthreads();
    }

    // ---- epilogue: normalize, split hi/lo, store ----
    float inv0 = 1.0f / l0r;
    float inv1 = 1.0f / l1r;
    const int r0 = b * SEQ + q0 + w * 16 + (l >> 2);
#pragma unroll
    for (int nt = 0; nt < 8; nt++) {
        size_t idx = (size_t)r0 * DMODEL + h * DKH + nt * 8 + (l & 3) * 2;
        uint32_t hA, lA, hB, lB;
        split2(O[nt][0] * inv0, O[nt][1] * inv0, hA, lA);
        split2(O[nt][2] * inv1, O[nt][3] * inv1, hB, lB);
        *(uint32_t*)(Oh_ + idx)              = hA;
        *(uint32_t*)(Ol_ + idx)              = lA;
        *(uint32_t*)(Oh_ + idx + 8 * DMODEL) = hB;
        *(uint32_t*)(Ol_ + idx + 8 * DMODEL) = lB;
    }
#undef AT_COPY_KV
}

// ---------------------------------------------------------------------------
extern "C" void kernel_launch(void* const* d_in, const int* in_sizes, int n_in,
                              void* d_out, int out_size)
{
    const float* x    = (const float*)d_in[0];
    const int*   mask = (const int*)  d_in[1];
    const float* Wq   = (const float*)d_in[2];
    const float* bq   = (const float*)d_in[3];
    const float* Wk   = (const float*)d_in[4];
    const float* bk   = (const float*)d_in[5];
    const float* Wv   = (const float*)d_in[6];
    const float* bv   = (const float*)d_in[7];
    const float* Wo   = (const float*)d_in[8];
    const float* bo   = (const float*)d_in[9];
    float* out = (float*)d_out;

    __nv_bfloat16 *xh, *xl, *wh, *wl, *qh, *ql, *kh, *kl, *vh, *vl, *ah, *al;
    cudaGetSymbolAddress((void**)&xh, g_xh);
    cudaGetSymbolAddress((void**)&xl, g_xl);
    cudaGetSymbolAddress((void**)&wh, g_wh);
    cudaGetSymbolAddress((void**)&wl, g_wl);
    cudaGetSymbolAddress((void**)&qh, g_qh);
    cudaGetSymbolAddress((void**)&ql, g_ql);
    cudaGetSymbolAddress((void**)&kh, g_kh);
    cudaGetSymbolAddress((void**)&kl, g_kl);
    cudaGetSymbolAddress((void**)&vh, g_vh);
    cudaGetSymbolAddress((void**)&vl, g_vl);
    cudaGetSymbolAddress((void**)&ah, g_ah);
    cudaGetSymbolAddress((void**)&al, g_al);

    cudaFuncSetAttribute(gemm_tc,
                         cudaFuncAttributeMaxDynamicSharedMemorySize, GEMM_DSMEM);
    cudaFuncSetAttribute(attn_tc,
                         cudaFuncAttributeMaxDynamicSharedMemorySize, AT_DSMEM);

    const int n4x = MR * DMODEL / 4;
    const int n4w = DD / 4;

    cvt_hilo<<<n4x / 256, 256>>>(x, xh, xl, n4x);
    dim3 gw(n4w / 256, 1, 4);
    cvt_hilo_w<<<gw, 256>>>(Wq, Wk, Wv, Wo, wh, wl, n4w);

    dim3 gg(MR / TM, DMODEL / TN);   // 64 x 8
    // Q projection: fold 1/sqrt(d_k) = 0.125 into the stored Q
    gemm_tc<<<gg, 256, GEMM_DSMEM>>>(xh, xl, wh + 0 * (size_t)DD, wl + 0 * (size_t)DD,
                                     bq, nullptr, qh, ql, 0.125f);
    gemm_tc<<<gg, 256, GEMM_DSMEM>>>(xh, xl, wh + 1 * (size_t)DD, wl + 1 * (size_t)DD,
                                     bk, nullptr, kh, kl, 1.0f);
    gemm_tc<<<gg, 256, GEMM_DSMEM>>>(xh, xl, wh + 2 * (size_t)DD, wl + 2 * (size_t)DD,
                                     bv, nullptr, vh, vl, 1.0f);

    dim3 ga(SEQ / 128, BATCH * NHEADS);   // 16 x 64
    attn_tc<<<ga, 256, AT_DSMEM>>>(qh, ql, kh, kl, vh, vl, mask, ah, al);

    gemm_tc<<<gg, 256, GEMM_DSMEM>>>(ah, al, wh + 3 * (size_t)DD, wl + 3 * (size_t)DD,
                                     bo, out, nullptr, nullptr, 1.0f);
}

// round 14
// speedup vs baseline: 1.6104x; 1.1276x over previous
#include <cuda_runtime.h>
#include <cuda_bf16.h>
#include <math.h>
#include <stdint.h>

#define DMODEL 1024
#define NHEADS 16
#define DKH    64
#define BATCH  4
#define SEQ    2048
#define MR     (BATCH * SEQ)   // 8192 rows
#define DD     (DMODEL * DMODEL)

// ---------------- scratch (allocation-free rule: __device__ globals) -------
static __device__ __nv_bfloat16 g_xh[(size_t)MR * DMODEL];
static __device__ __nv_bfloat16 g_xl[(size_t)MR * DMODEL];
static __device__ __nv_bfloat16 g_wh[(size_t)4 * DD];
static __device__ __nv_bfloat16 g_wl[(size_t)4 * DD];
static __device__ __nv_bfloat16 g_qh[(size_t)MR * DMODEL];
static __device__ __nv_bfloat16 g_ql[(size_t)MR * DMODEL];
static __device__ __nv_bfloat16 g_kh[(size_t)MR * DMODEL];
static __device__ __nv_bfloat16 g_kl[(size_t)MR * DMODEL];
static __device__ __nv_bfloat16 g_vh[(size_t)MR * DMODEL];
static __device__ __nv_bfloat16 g_vl[(size_t)MR * DMODEL];
static __device__ __nv_bfloat16 g_ah[(size_t)MR * DMODEL];
static __device__ __nv_bfloat16 g_al[(size_t)MR * DMODEL];

// ---------------- PTX helpers (baseline, legal on compute_103) -------------
__device__ __forceinline__ uint32_t smem_u32(const void* p) {
    uint32_t a;
    asm("{ .reg .u64 t; cvta.to.shared.u64 t, %1; cvt.u32.u64 %0, t; }"
        : "=r"(a) : "l"(p));
    return a;
}

__device__ __forceinline__ void cp16(uint32_t dst, const void* src) {
    asm volatile("cp.async.cg.shared.global [%0], [%1], 16;\n"
                 :: "r"(dst), "l"(src) : "memory");
}
#define CP_COMMIT() asm volatile("cp.async.commit_group;\n" ::: "memory")
#define CP_WAIT(n)  asm volatile("cp.async.wait_group %0;\n" :: "n"(n) : "memory")

__device__ __forceinline__ void ldm4(uint32_t* r, uint32_t addr) {
    asm volatile("ldmatrix.sync.aligned.m8n8.x4.shared.b16 {%0,%1,%2,%3}, [%4];"
                 : "=r"(r[0]), "=r"(r[1]), "=r"(r[2]), "=r"(r[3]) : "r"(addr));
}

__device__ __forceinline__ void ldm4t(uint32_t* r, uint32_t addr) {
    asm volatile("ldmatrix.sync.aligned.m8n8.x4.trans.shared.b16 {%0,%1,%2,%3}, [%4];"
                 : "=r"(r[0]), "=r"(r[1]), "=r"(r[2]), "=r"(r[3]) : "r"(addr));
}

__device__ __forceinline__ void mma_bf16(float* c, const uint32_t* a,
                                         uint32_t b0, uint32_t b1) {
    asm volatile(
        "mma.sync.aligned.m16n8k16.row.col.f32.bf16.bf16.f32 "
        "{%0,%1,%2,%3}, {%4,%5,%6,%7}, {%8,%9}, {%0,%1,%2,%3};"
        : "+f"(c[0]), "+f"(c[1]), "+f"(c[2]), "+f"(c[3])
        : "r"(a[0]), "r"(a[1]), "r"(a[2]), "r"(a[3]), "r"(b0), "r"(b1));
}

// split fp32 pair into packed bf16 hi (truncated) + bf16 lo (rn of residual)
__device__ __forceinline__ void split2(float v0, float v1, uint32_t& h, uint32_t& l) {
    uint32_t b0 = __float_as_uint(v0), b1 = __float_as_uint(v1);
    h = __byte_perm(b0, b1, 0x7632);
    float r0 = v0 - __uint_as_float(b0 & 0xFFFF0000u);
    float r1 = v1 - __uint_as_float(b1 & 0xFFFF0000u);
    asm("cvt.rn.bf16x2.f32 %0, %1, %2;" : "=r"(l) : "f"(r1), "f"(r0));
}

// pack fp32 pair to bf16x2 (round-to-nearest, no residual)
__device__ __forceinline__ uint32_t pack2(float v0, float v1) {
    uint32_t r;
    asm("cvt.rn.bf16x2.f32 %0, %1, %2;" : "=r"(r) : "f"(v1), "f"(v0));
    return r;
}

// SW128 swizzle for 128B rows
#define SWZ128(o) ((o) ^ (((o) >> 3) & 0x70))
// swizzle for 64B rows
__device__ __forceinline__ uint32_t swz64(int row, int c16) {
    return (uint32_t)(row * 64 + ((c16 ^ ((row >> 1) & 3)) << 4));
}

// ---------------- fp32 -> (bf16 hi, bf16 lo) conversion --------------------
__global__ __launch_bounds__(256) void cvt_hilo(
    const float* __restrict__ in,
    __nv_bfloat16* __restrict__ hi, __nv_bfloat16* __restrict__ lo, int n4)
{
    int i = blockIdx.x * 256 + threadIdx.x;
    if (i >= n4) return;
    float4 v = ((const float4*)in)[i];
    uint32_t h0, l0, h1, l1;
    split2(v.x, v.y, h0, l0);
    split2(v.z, v.w, h1, l1);
    uint2 hh, ll;
    hh.x = h0; hh.y = h1;
    ll.x = l0; ll.y = l1;
    ((uint2*)hi)[i] = hh;
    ((uint2*)lo)[i] = ll;
}

// all 4 weight matrices in one launch (z selects source)
__global__ __launch_bounds__(256) void cvt_hilo_w(
    const float* __restrict__ w0, const float* __restrict__ w1,
    const float* __restrict__ w2, const float* __restrict__ w3,
    __nv_bfloat16* __restrict__ hi, __nv_bfloat16* __restrict__ lo, int n4)
{
    int i = blockIdx.x * 256 + threadIdx.x;
    if (i >= n4) return;
    const int z = blockIdx.z;
    const float* in = (z == 0) ? w0 : ((z == 1) ? w1 : ((z == 2) ? w2 : w3));
    float4 v = ((const float4*)in)[i];
    uint32_t h0, l0, h1, l1;
    split2(v.x, v.y, h0, l0);
    split2(v.z, v.w, h1, l1);
    uint2 hh, ll;
    hh.x = h0; hh.y = h1;
    ll.x = l0; ll.y = l1;
    ((uint2*)(hi + (size_t)z * DD))[i] = hh;
    ((uint2*)(lo + (size_t)z * DD))[i] = ll;
}

// ---------------- bf16x3 GEMM (mma.sync): C[M,N]=(A@W^T+bias)*scale --------
// tile 128x128, KB=32, double-buffered cp.async, 256 threads, 2 CTAs/SM
// (R7-vs-R9 A/B: (256,2)+64KB beat (256,1)+64KB by 107us like-for-like).
// Register-lean mainloop: A fragments hoisted (16 regs), B streamed (8 regs)
// so the 128-reg cap at occupancy 2 does not spill.
#define TM 128
#define TN 128
#define KB_F   32
#define NKB_F  (DMODEL / KB_F)         // 32
#define FSTG   (TM * KB_F * 2)         // 8192 B per bf16 submatrix
#define STAGE_F (4 * FSTG)             // 32768
#define GEMM_DSMEM (2 * STAGE_F)       // 65536 -> 2 CTAs/SM

__device__ __forceinline__ void copy_tiles_f(
    const __nv_bfloat16* __restrict__ Ah, const __nv_bfloat16* __restrict__ Al,
    const __nv_bfloat16* __restrict__ Wh, const __nv_bfloat16* __restrict__ Wl,
    int m0, int n0, int kb, uint32_t base, int tid)
{
    const int koff = kb * KB_F;
#pragma unroll
    for (int i = 0; i < 2; i++) {
        int c   = tid + i * 256;
        int row = c >> 2;
        int c16 = c & 3;
        uint32_t sw = base + swz64(row, c16);
        cp16(sw,            Ah + (size_t)(m0 + row) * DMODEL + koff + c16 * 8);
        cp16(sw + FSTG,     Al + (size_t)(m0 + row) * DMODEL + koff + c16 * 8);
        cp16(sw + 2 * FSTG, Wh + (size_t)(n0 + row) * DMODEL + koff + c16 * 8);
        cp16(sw + 3 * FSTG, Wl + (size_t)(n0 + row) * DMODEL + koff + c16 * 8);
    }
}

__global__ __launch_bounds__(256, 2) void gemm_f(
    const __nv_bfloat16* __restrict__ Ah, const __nv_bfloat16* __restrict__ Al,
    const __nv_bfloat16* __restrict__ Wh0, const __nv_bfloat16* __restrict__ Wl0,
    const float* __restrict__ b0p, const float* __restrict__ b1p,
    const float* __restrict__ b2p,
    __nv_bfloat16* __restrict__ Ch0, __nv_bfloat16* __restrict__ Cl0,
    __nv_bfloat16* __restrict__ Ch1, __nv_bfloat16* __restrict__ Cl1,
    __nv_bfloat16* __restrict__ Ch2, __nv_bfloat16* __restrict__ Cl2,
    float* __restrict__ C, float scale0)
{
    extern __shared__ char dsm[];
    const int tid = threadIdx.x;
    const int wid = tid >> 5;
    const int lid = tid & 31;
    const int m0  = blockIdx.x * TM;
    const int n0  = blockIdx.y * TN;
    const int z   = blockIdx.z;

    const __nv_bfloat16* Wh = Wh0 + (size_t)z * DD;
    const __nv_bfloat16* Wl = Wl0 + (size_t)z * DD;
    const float* bias = (z == 0) ? b0p : ((z == 1) ? b1p : b2p);
    __nv_bfloat16* Ch = (z == 0) ? Ch0 : ((z == 1) ? Ch1 : Ch2);
    __nv_bfloat16* Cl = (z == 0) ? Cl0 : ((z == 1) ? Cl1 : Cl2);
    const float scale = (z == 0) ? scale0 : 1.0f;

    const uint32_t abase = smem_u32(dsm);

    const int wm = wid >> 1;   // 0..3 (32-row strip)
    const int wn = wid & 1;    // 0..1 (64-col strip)

    float acc[2][8][4];
#pragma unroll
    for (int mt = 0; mt < 2; mt++)
#pragma unroll
        for (int nt = 0; nt < 8; nt++)
#pragma unroll
            for (int j = 0; j < 4; j++) acc[mt][nt][j] = 0.0f;

    const int lrow  = (lid & 7) + ((lid >> 3) & 1) * 8;
    const int lhalf = lid >> 4;

    copy_tiles_f(Ah, Al, Wh, Wl, m0, n0, 0, abase, tid);
    CP_COMMIT();

    for (int kb = 0; kb < NKB_F; kb++) {
        const uint32_t sbase = abase + (uint32_t)(kb & 1) * STAGE_F;
        if (kb + 1 < NKB_F) {
            copy_tiles_f(Ah, Al, Wh, Wl, m0, n0, kb + 1,
                         abase + (uint32_t)((kb + 1) & 1) * STAGE_F, tid);
            CP_COMMIT();
            CP_WAIT(1);
        } else {
            CP_WAIT(0);
        }
        __syncthreads();

#pragma unroll
        for (int ks = 0; ks < 2; ks++) {
            const int chunk = ks * 2 + lhalf;
            // hoist A fragments for both 16-row subtiles (16 regs live)
            uint32_t ah[2][4], al[2][4];
#pragma unroll
            for (int mt = 0; mt < 2; mt++) {
                uint32_t aoff = swz64(wm * 32 + mt * 16 + lrow, chunk);
                ldm4(ah[mt], sbase + aoff);
                ldm4(al[mt], sbase + FSTG + aoff);
            }
            // stream B fragments (8 regs live at a time)
#pragma unroll
            for (int nt = 0; nt < 4; nt++) {
                uint32_t boff = swz64(wn * 64 + nt * 16 + lrow, chunk);
                uint32_t bh[4], bl[4];
                ldm4(bh, sbase + 2 * FSTG + boff);
                ldm4(bl, sbase + 3 * FSTG + boff);
#pragma unroll
                for (int mt = 0; mt < 2; mt++) {
                    mma_bf16(acc[mt][2 * nt + 0], ah[mt], bh[0], bh[2]);
                    mma_bf16(acc[mt][2 * nt + 1], ah[mt], bh[1], bh[3]);
                    mma_bf16(acc[mt][2 * nt + 0], ah[mt], bl[0], bl[2]);
                    mma_bf16(acc[mt][2 * nt + 1], ah[mt], bl[1], bl[3]);
                    mma_bf16(acc[mt][2 * nt + 0], al[mt], bh[0], bh[2]);
                    mma_bf16(acc[mt][2 * nt + 1], al[mt], bh[1], bh[3]);
                }
            }
        }
        __syncthreads();
    }

#pragma unroll
    for (int mt = 0; mt < 2; mt++) {
        int r0 = m0 + wm * 32 + mt * 16 + (lid >> 2);
#pragma unroll
        for (int nt = 0; nt < 8; nt++) {
            int c0 = n0 + wn * 64 + nt * 8 + (lid & 3) * 2;
            float bb0 = bias[c0], bb1 = bias[c0 + 1];
            float u0 = (acc[mt][nt][0] + bb0) * scale;
            float u1 = (acc[mt][nt][1] + bb1) * scale;
            float v0 = (acc[mt][nt][2] + bb0) * scale;
            float v1 = (acc[mt][nt][3] + bb1) * scale;
            size_t i0 = (size_t)r0 * DMODEL + c0;
            size_t i1 = (size_t)(r0 + 8) * DMODEL + c0;
            if (Ch) {
                uint32_t h0, l0, h1, l1;
                split2(u0, u1, h0, l0);
                split2(v0, v1, h1, l1);
                *(uint32_t*)(Ch + i0) = h0;
                *(uint32_t*)(Cl + i0) = l0;
                *(uint32_t*)(Ch + i1) = h1;
                *(uint32_t*)(Cl + i1) = l1;
            } else {
                float2 u; u.x = u0; u.y = u1;
                float2 v; v.x = v0; v.y = v1;
                *(float2*)(C + i0) = u;
                *(float2*)(C + i1) = v;
            }
        }
    }
}

// ---------------------------------------------------------------------------
// Tensor-core FlashAttention-2. QK^T: bf16x3. PV: 2-pass (ph*vh + ph*vl) —
// validated R13: -12% attn time, rel_err 5.76e-4 deterministic (fixed seed).
// __expf softmax, 1/sqrt(d_k) folded into Q.
// CTA = 128 q-rows x one (b,h). 8 warps x 16 q-rows. Key tiles of 64.
// ---------------------------------------------------------------------------
#define AT_STG   33792
#define AT_KVOFF 32768
#define AT_DSMEM (AT_KVOFF + 2 * AT_STG)     // 100352

__global__ __launch_bounds__(256, 1) void attn_tc(
    const __nv_bfloat16* __restrict__ Qh_, const __nv_bfloat16* __restrict__ Ql_,
    const __nv_bfloat16* __restrict__ Kh_, const __nv_bfloat16* __restrict__ Kl_,
    const __nv_bfloat16* __restrict__ Vh_, const __nv_bfloat16* __restrict__ Vl_,
    const int* __restrict__ mask,
    __nv_bfloat16* __restrict__ Oh_, __nv_bfloat16* __restrict__ Ol_)
{
    extern __shared__ char sm[];
    const uint32_t sb = smem_u32(sm);

    const int tid = threadIdx.x;
    const int w   = tid >> 5;
    const int l   = tid & 31;
    const int bh  = blockIdx.y;
    const int b   = bh >> 4;
    const int h   = bh & 15;
    const int q0  = blockIdx.x * 128;

    const size_t rowQ  = ((size_t)(b * SEQ + q0)) * DMODEL + h * DKH;
    const size_t rowK0 = ((size_t)(b * SEQ)) * DMODEL + h * DKH;
    const int*   mg    = mask + b * SEQ;

    // --- Q tiles (hi/lo) -> smem, group 0 ---
#pragma unroll
    for (int i = 0; i < 4; i++) {
        int c   = tid + i * 256;
        int row = c >> 3;
        int c8  = c & 7;
        uint32_t sw = SWZ128(row * 128 + c8 * 16);
        cp16(sb + sw,         Qh_ + rowQ + (size_t)row * DMODEL + c8 * 8);
        cp16(sb + 16384 + sw, Ql_ + rowQ + (size_t)row * DMODEL + c8 * 8);
    }
    CP_COMMIT();

#define AT_COPY_KV(kb_, s_) do {                                                 \
    uint32_t kvb_ = sb + AT_KVOFF + (uint32_t)(s_) * AT_STG;                     \
    {                                                                            \
        int c_   = tid;                                                          \
        int row_ = c_ >> 3;                                                      \
        int c8_  = c_ & 7;                                                       \
        uint32_t sw_ = SWZ128(row_ * 128 + c8_ * 16);                            \
        size_t g_ = rowK0 + (size_t)((kb_) * 64 + row_) * DMODEL + c8_ * 8;      \
        cp16(kvb_ + sw_,         Kh_ + g_);                                      \
        cp16(kvb_ + 8192 + sw_,  Kl_ + g_);                                      \
        cp16(kvb_ + 16384 + sw_, Vh_ + g_);                                      \
        cp16(kvb_ + 24576 + sw_, Vl_ + g_);                                      \
    }                                                                            \
    {                                                                            \
        int c_   = tid + 256;                                                    \
        int row_ = c_ >> 3;                                                      \
        int c8_  = c_ & 7;                                                       \
        uint32_t sw_ = SWZ128(row_ * 128 + c8_ * 16);                            \
        size_t g_ = rowK0 + (size_t)((kb_) * 64 + row_) * DMODEL + c8_ * 8;      \
        cp16(kvb_ + sw_,         Kh_ + g_);                                      \
        cp16(kvb_ + 8192 + sw_,  Kl_ + g_);                                      \
        cp16(kvb_ + 16384 + sw_, Vh_ + g_);                                      \
        cp16(kvb_ + 24576 + sw_, Vl_ + g_);                                      \
    }                                                                            \
    if (tid < 16) cp16(kvb_ + 32768 + tid * 16, mg + (kb_) * 64 + tid * 4);      \
} while (0)

    AT_COPY_KV(0, 0);
    CP_COMMIT();

    CP_WAIT(1);
    __syncthreads();

    // --- preload Q fragments (held across the whole loop) ---
    const int lrow = (l & 7) + ((l >> 3) & 1) * 8;
    const int lkb  = (l >> 4) * 16;
    uint32_t qh[4][4], ql[4][4];
#pragma unroll
    for (int kt = 0; kt < 4; kt++) {
        uint32_t qa = sb + SWZ128((w * 16 + lrow) * 128 + kt * 32 + lkb);
        ldm4(qh[kt], qa);
        ldm4(ql[kt], qa + 16384);
    }

    float O[8][4];
    float S[8][4];
    float m0r = -INFINITY, m1r = -INFINITY, l0r = 0.0f, l1r = 0.0f;
#pragma unroll
    for (int nt = 0; nt < 8; nt++)
#pragma unroll
        for (int j = 0; j < 4; j++) O[nt][j] = 0.0f;

    for (int kb = 0; kb < SEQ / 64; kb++) {
        const int s = kb & 1;
        if (kb + 1 < SEQ / 64) {
            AT_COPY_KV(kb + 1, s ^ 1);
            CP_COMMIT();
            CP_WAIT(1);
        } else {
            CP_WAIT(0);
        }
        __syncthreads();

        const uint32_t kvb = sb + AT_KVOFF + (uint32_t)s * AT_STG;
        const char* kvc = sm + AT_KVOFF + (size_t)s * AT_STG;

        // ---- S = Q @ K^T (bf16x3) ----
#pragma unroll
        for (int nt = 0; nt < 8; nt++)
#pragma unroll
            for (int j = 0; j < 4; j++) S[nt][j] = 0.0f;

#pragma unroll
        for (int kt = 0; kt < 4; kt++) {
#pragma unroll
            for (int np = 0; np < 4; np++) {
                uint32_t ka = kvb + SWZ128((np * 16 + lrow) * 128 + kt * 32 + lkb);
                uint32_t kh[4], kl[4];
                ldm4(kh, ka);
                ldm4(kl, ka + 8192);
                mma_bf16(S[2 * np + 0], qh[kt], kh[0], kh[2]);
                mma_bf16(S[2 * np + 0], qh[kt], kl[0], kl[2]);
                mma_bf16(S[2 * np + 0], ql[kt], kh[0], kh[2]);
                mma_bf16(S[2 * np + 1], qh[kt], kh[1], kh[3]);
                mma_bf16(S[2 * np + 1], qh[kt], kl[1], kl[3]);
                mma_bf16(S[2 * np + 1], ql[kt], kh[1], kh[3]);
            }
        }

        // ---- mask + online softmax ----
        const int* smask = (const int*)(kvc + 32768);
        float mx0 = -INFINITY, mx1 = -INFINITY;
#pragma unroll
        for (int nt = 0; nt < 8; nt++) {
            int2 mk = *(const int2*)(smask + nt * 8 + (l & 3) * 2);
            if (mk.x == 0) { S[nt][0] = -1e9f; S[nt][2] = -1e9f; }
            if (mk.y == 0) { S[nt][1] = -1e9f; S[nt][3] = -1e9f; }
            mx0 = fmaxf(mx0, fmaxf(S[nt][0], S[nt][1]));
            mx1 = fmaxf(mx1, fmaxf(S[nt][2], S[nt][3]));
        }
        mx0 = fmaxf(mx0, __shfl_xor_sync(0xffffffffu, mx0, 1));
        mx0 = fmaxf(mx0, __shfl_xor_sync(0xffffffffu, mx0, 2));
        mx1 = fmaxf(mx1, __shfl_xor_sync(0xffffffffu, mx1, 1));
        mx1 = fmaxf(mx1, __shfl_xor_sync(0xffffffffu, mx1, 2));

        float mn0 = fmaxf(m0r, mx0);
        float mn1 = fmaxf(m1r, mx1);
        float a0 = __expf(m0r - mn0);
        float a1 = __expf(m1r - mn1);
        m0r = mn0; m1r = mn1;

        float sum0 = 0.0f, sum1 = 0.0f;
#pragma unroll
        for (int nt = 0; nt < 8; nt++) {
            S[nt][0] = __expf(S[nt][0] - mn0);
            S[nt][1] = __expf(S[nt][1] - mn0);
            S[nt][2] = __expf(S[nt][2] - mn1);
            S[nt][3] = __expf(S[nt][3] - mn1);
            sum0 += S[nt][0] + S[nt][1];
            sum1 += S[nt][2] + S[nt][3];
        }
        sum0 += __shfl_xor_sync(0xffffffffu, sum0, 1);
        sum0 += __shfl_xor_sync(0xffffffffu, sum0, 2);
        sum1 += __shfl_xor_sync(0xffffffffu, sum1, 1);
        sum1 += __shfl_xor_sync(0xffffffffu, sum1, 2);
        l0r = l0r * a0 + sum0;
        l1r = l1r * a1 + sum1;

#pragma unroll
        for (int nt = 0; nt < 8; nt++) {
            O[nt][0] *= a0; O[nt][1] *= a0;
            O[nt][2] *= a1; O[nt][3] *= a1;
        }

        // ---- O += P @ V (2-pass: ph*vh + ph*vl) ----
#pragma unroll
        for (int kt = 0; kt < 4; kt++) {
            uint32_t ph[4];
            ph[0] = pack2(S[2 * kt + 0][0], S[2 * kt + 0][1]);
            ph[1] = pack2(S[2 * kt + 0][2], S[2 * kt + 0][3]);
            ph[2] = pack2(S[2 * kt + 1][0], S[2 * kt + 1][1]);
            ph[3] = pack2(S[2 * kt + 1][2], S[2 * kt + 1][3]);
#pragma unroll
            for (int dp = 0; dp < 4; dp++) {
                uint32_t va = kvb + 16384 + SWZ128((kt * 16 + lrow) * 128 + dp * 32 + lkb);
                uint32_t vh[4], vl[4];
                ldm4t(vh, va);
                ldm4t(vl, va + 8192);
                mma_bf16(O[2 * dp + 0], ph, vh[0], vh[1]);
                mma_bf16(O[2 * dp + 0], ph, vl[0], vl[1]);
                mma_bf16(O[2 * dp + 1], ph, vh[2], vh[3]);
                mma_bf16(O[2 * dp + 1], ph, vl[2], vl[3]);
            }
        }
        __syncthreads();
    }

    // ---- epilogue: normalize, split hi/lo, store ----
    float inv0 = 1.0f / l0r;
    float inv1 = 1.0f / l1r;
    const int r0 = b * SEQ + q0 + w * 16 + (l >> 2);
#pragma unroll
    for (int nt = 0; nt < 8; nt++) {
        size_t idx = (size_t)r0 * DMODEL + h * DKH + nt * 8 + (l & 3) * 2;
        uint32_t hA, lA, hB, lB;
        split2(O[nt][0] * inv0, O[nt][1] * inv0, hA, lA);
        split2(O[nt][2] * inv1, O[nt][3] * inv1, hB, lB);
        *(uint32_t*)(Oh_ + idx)              = hA;
        *(uint32_t*)(Ol_ + idx)              = lA;
        *(uint32_t*)(Oh_ + idx + 8 * DMODEL) = hB;
        *(uint32_t*)(Ol_ + idx + 8 * DMODEL) = lB;
    }
#undef AT_COPY_KV
}

// ---------------------------------------------------------------------------
extern "C" void kernel_launch(void* const* d_in, const int* in_sizes, int n_in,
                              void* d_out, int out_size)
{
    const float* x    = (const float*)d_in[0];
    const int*   mask = (const int*)  d_in[1];
    const float* Wq   = (const float*)d_in[2];
    const float* bq   = (const float*)d_in[3];
    const float* Wk   = (const float*)d_in[4];
    const float* bk   = (const float*)d_in[5];
    const float* Wv   = (const float*)d_in[6];
    const float* bv   = (const float*)d_in[7];
    const float* Wo   = (const float*)d_in[8];
    const float* bo   = (const float*)d_in[9];
    float* out = (float*)d_out;

    __nv_bfloat16 *xh, *xl, *wh, *wl, *qh, *ql, *kh, *kl, *vh, *vl, *ah, *al;
    cudaGetSymbolAddress((void**)&xh, g_xh);
    cudaGetSymbolAddress((void**)&xl, g_xl);
    cudaGetSymbolAddress((void**)&wh, g_wh);
    cudaGetSymbolAddress((void**)&wl, g_wl);
    cudaGetSymbolAddress((void**)&qh, g_qh);
    cudaGetSymbolAddress((void**)&ql, g_ql);
    cudaGetSymbolAddress((void**)&kh, g_kh);
    cudaGetSymbolAddress((void**)&kl, g_kl);
    cudaGetSymbolAddress((void**)&vh, g_vh);
    cudaGetSymbolAddress((void**)&vl, g_vl);
    cudaGetSymbolAddress((void**)&ah, g_ah);
    cudaGetSymbolAddress((void**)&al, g_al);

    cudaFuncSetAttribute(gemm_f,
                         cudaFuncAttributeMaxDynamicSharedMemorySize, GEMM_DSMEM);
    cudaFuncSetAttribute(attn_tc,
                         cudaFuncAttributeMaxDynamicSharedMemorySize, AT_DSMEM);

    const int n4x = MR * DMODEL / 4;
    const int n4w = DD / 4;

    cvt_hilo<<<n4x / 256, 256>>>(x, xh, xl, n4x);
    dim3 gw(n4w / 256, 1, 4);
    cvt_hilo_w<<<gw, 256>>>(Wq, Wk, Wv, Wo, wh, wl, n4w);

    // merged QKV projection: z = 0/1/2 -> Q/K/V. Q gets 1/sqrt(dk) scale.
    dim3 gqkv(MR / TM, DMODEL / TN, 3);   // 64 x 8 x 3
    gemm_f<<<gqkv, 256, GEMM_DSMEM>>>(xh, xl, wh, wl, bq, bk, bv,
                                      qh, ql, kh, kl, vh, vl,
                                      nullptr, 0.125f);

    dim3 ga(SEQ / 128, BATCH * NHEADS);   // 16 x 64
    attn_tc<<<ga, 256, AT_DSMEM>>>(qh, ql, kh, kl, vh, vl, mask, ah, al);

    // output projection (z extent 1, fp32 output)
    dim3 go(MR / TM, DMODEL / TN, 1);
    gemm_f<<<go, 256, GEMM_DSMEM>>>(ah, al, wh + 3 * (size_t)DD, wl + 3 * (size_t)DD,
                                    bo, bo, bo,
                                    nullptr, nullptr, nullptr, nullptr, nullptr, nullptr,
                                    out, 1.0f);
}

// round 15
// speedup vs baseline: 1.6878x; 1.0480x over previous
#include <cuda_runtime.h>
#include <cuda_bf16.h>
#include <math.h>
#include <stdint.h>

#define DMODEL 1024
#define NHEADS 16
#define DKH    64
#define BATCH  4
#define SEQ    2048
#define MR     (BATCH * SEQ)   // 8192 rows
#define DD     (DMODEL * DMODEL)

// ---------------- scratch (allocation-free rule: __device__ globals) -------
static __device__ __nv_bfloat16 g_xh[(size_t)MR * DMODEL];
static __device__ __nv_bfloat16 g_xl[(size_t)MR * DMODEL];
static __device__ __nv_bfloat16 g_wh[(size_t)4 * DD];
static __device__ __nv_bfloat16 g_wl[(size_t)4 * DD];
static __device__ __nv_bfloat16 g_qh[(size_t)MR * DMODEL];
static __device__ __nv_bfloat16 g_ql[(size_t)MR * DMODEL];
static __device__ __nv_bfloat16 g_kh[(size_t)MR * DMODEL];
static __device__ __nv_bfloat16 g_kl[(size_t)MR * DMODEL];
static __device__ __nv_bfloat16 g_vh[(size_t)MR * DMODEL];
static __device__ __nv_bfloat16 g_vl[(size_t)MR * DMODEL];
static __device__ __nv_bfloat16 g_ah[(size_t)MR * DMODEL];
static __device__ __nv_bfloat16 g_al[(size_t)MR * DMODEL];

// ---------------- PTX helpers (baseline, legal on compute_103) -------------
__device__ __forceinline__ uint32_t smem_u32(const void* p) {
    uint32_t a;
    asm("{ .reg .u64 t; cvta.to.shared.u64 t, %1; cvt.u32.u64 %0, t; }"
        : "=r"(a) : "l"(p));
    return a;
}

__device__ __forceinline__ void cp16(uint32_t dst, const void* src) {
    asm volatile("cp.async.cg.shared.global [%0], [%1], 16;\n"
                 :: "r"(dst), "l"(src) : "memory");
}
#define CP_COMMIT() asm volatile("cp.async.commit_group;\n" ::: "memory")
#define CP_WAIT(n)  asm volatile("cp.async.wait_group %0;\n" :: "n"(n) : "memory")

__device__ __forceinline__ void ldm4(uint32_t* r, uint32_t addr) {
    asm volatile("ldmatrix.sync.aligned.m8n8.x4.shared.b16 {%0,%1,%2,%3}, [%4];"
                 : "=r"(r[0]), "=r"(r[1]), "=r"(r[2]), "=r"(r[3]) : "r"(addr));
}

__device__ __forceinline__ void ldm4t(uint32_t* r, uint32_t addr) {
    asm volatile("ldmatrix.sync.aligned.m8n8.x4.trans.shared.b16 {%0,%1,%2,%3}, [%4];"
                 : "=r"(r[0]), "=r"(r[1]), "=r"(r[2]), "=r"(r[3]) : "r"(addr));
}

__device__ __forceinline__ void mma_bf16(float* c, const uint32_t* a,
                                         uint32_t b0, uint32_t b1) {
    asm volatile(
        "mma.sync.aligned.m16n8k16.row.col.f32.bf16.bf16.f32 "
        "{%0,%1,%2,%3}, {%4,%5,%6,%7}, {%8,%9}, {%0,%1,%2,%3};"
        : "+f"(c[0]), "+f"(c[1]), "+f"(c[2]), "+f"(c[3])
        : "r"(a[0]), "r"(a[1]), "r"(a[2]), "r"(a[3]), "r"(b0), "r"(b1));
}

// split fp32 pair into packed bf16 hi (truncated) + bf16 lo (rn of residual)
__device__ __forceinline__ void split2(float v0, float v1, uint32_t& h, uint32_t& l) {
    uint32_t b0 = __float_as_uint(v0), b1 = __float_as_uint(v1);
    h = __byte_perm(b0, b1, 0x7632);
    float r0 = v0 - __uint_as_float(b0 & 0xFFFF0000u);
    float r1 = v1 - __uint_as_float(b1 & 0xFFFF0000u);
    asm("cvt.rn.bf16x2.f32 %0, %1, %2;" : "=r"(l) : "f"(r1), "f"(r0));
}

// pack fp32 pair to bf16x2 (round-to-nearest, no residual)
__device__ __forceinline__ uint32_t pack2(float v0, float v1) {
    uint32_t r;
    asm("cvt.rn.bf16x2.f32 %0, %1, %2;" : "=r"(r) : "f"(v1), "f"(v0));
    return r;
}

// SW128 swizzle for 128B rows
#define SWZ128(o) ((o) ^ (((o) >> 3) & 0x70))
// swizzle for 64B rows
__device__ __forceinline__ uint32_t swz64(int row, int c16) {
    return (uint32_t)(row * 64 + ((c16 ^ ((row >> 1) & 3)) << 4));
}

// ---------------- fp32 -> (bf16 hi, bf16 lo) conversion --------------------
__global__ __launch_bounds__(256) void cvt_hilo(
    const float* __restrict__ in,
    __nv_bfloat16* __restrict__ hi, __nv_bfloat16* __restrict__ lo, int n4)
{
    int i = blockIdx.x * 256 + threadIdx.x;
    if (i >= n4) return;
    float4 v = ((const float4*)in)[i];
    uint32_t h0, l0, h1, l1;
    split2(v.x, v.y, h0, l0);
    split2(v.z, v.w, h1, l1);
    uint2 hh, ll;
    hh.x = h0; hh.y = h1;
    ll.x = l0; ll.y = l1;
    ((uint2*)hi)[i] = hh;
    ((uint2*)lo)[i] = ll;
}

// all 4 weight matrices in one launch (z selects source)
__global__ __launch_bounds__(256) void cvt_hilo_w(
    const float* __restrict__ w0, const float* __restrict__ w1,
    const float* __restrict__ w2, const float* __restrict__ w3,
    __nv_bfloat16* __restrict__ hi, __nv_bfloat16* __restrict__ lo, int n4)
{
    int i = blockIdx.x * 256 + threadIdx.x;
    if (i >= n4) return;
    const int z = blockIdx.z;
    const float* in = (z == 0) ? w0 : ((z == 1) ? w1 : ((z == 2) ? w2 : w3));
    float4 v = ((const float4*)in)[i];
    uint32_t h0, l0, h1, l1;
    split2(v.x, v.y, h0, l0);
    split2(v.z, v.w, h1, l1);
    uint2 hh, ll;
    hh.x = h0; hh.y = h1;
    ll.x = l0; ll.y = l1;
    ((uint2*)(hi + (size_t)z * DD))[i] = hh;
    ((uint2*)(lo + (size_t)z * DD))[i] = ll;
}

// ---------------- bf16x3 GEMM (mma.sync): C[M,N]=(A@W^T+bias)*scale --------
// tile 128x128, KB=32, double-buffered cp.async, 256 threads, 2 CTAs/SM
// (validated R14: -140us vs (256,1)). Register-lean mainloop.
#define TM 128
#define TN 128
#define KB_F   32
#define NKB_F  (DMODEL / KB_F)         // 32
#define FSTG   (TM * KB_F * 2)         // 8192 B per bf16 submatrix
#define STAGE_F (4 * FSTG)             // 32768
#define GEMM_DSMEM (2 * STAGE_F)       // 65536 -> 2 CTAs/SM

__device__ __forceinline__ void copy_tiles_f(
    const __nv_bfloat16* __restrict__ Ah, const __nv_bfloat16* __restrict__ Al,
    const __nv_bfloat16* __restrict__ Wh, const __nv_bfloat16* __restrict__ Wl,
    int m0, int n0, int kb, uint32_t base, int tid)
{
    const int koff = kb * KB_F;
#pragma unroll
    for (int i = 0; i < 2; i++) {
        int c   = tid + i * 256;
        int row = c >> 2;
        int c16 = c & 3;
        uint32_t sw = base + swz64(row, c16);
        cp16(sw,            Ah + (size_t)(m0 + row) * DMODEL + koff + c16 * 8);
        cp16(sw + FSTG,     Al + (size_t)(m0 + row) * DMODEL + koff + c16 * 8);
        cp16(sw + 2 * FSTG, Wh + (size_t)(n0 + row) * DMODEL + koff + c16 * 8);
        cp16(sw + 3 * FSTG, Wl + (size_t)(n0 + row) * DMODEL + koff + c16 * 8);
    }
}

__global__ __launch_bounds__(256, 2) void gemm_f(
    const __nv_bfloat16* __restrict__ Ah, const __nv_bfloat16* __restrict__ Al,
    const __nv_bfloat16* __restrict__ Wh0, const __nv_bfloat16* __restrict__ Wl0,
    const float* __restrict__ b0p, const float* __restrict__ b1p,
    const float* __restrict__ b2p,
    __nv_bfloat16* __restrict__ Ch0, __nv_bfloat16* __restrict__ Cl0,
    __nv_bfloat16* __restrict__ Ch1, __nv_bfloat16* __restrict__ Cl1,
    __nv_bfloat16* __restrict__ Ch2, __nv_bfloat16* __restrict__ Cl2,
    float* __restrict__ C, float scale0)
{
    extern __shared__ char dsm[];
    const int tid = threadIdx.x;
    const int wid = tid >> 5;
    const int lid = tid & 31;
    const int m0  = blockIdx.x * TM;
    const int n0  = blockIdx.y * TN;
    const int z   = blockIdx.z;

    const __nv_bfloat16* Wh = Wh0 + (size_t)z * DD;
    const __nv_bfloat16* Wl = Wl0 + (size_t)z * DD;
    const float* bias = (z == 0) ? b0p : ((z == 1) ? b1p : b2p);
    __nv_bfloat16* Ch = (z == 0) ? Ch0 : ((z == 1) ? Ch1 : Ch2);
    __nv_bfloat16* Cl = (z == 0) ? Cl0 : ((z == 1) ? Cl1 : Cl2);
    const float scale = (z == 0) ? scale0 : 1.0f;

    const uint32_t abase = smem_u32(dsm);

    const int wm = wid >> 1;   // 0..3 (32-row strip)
    const int wn = wid & 1;    // 0..1 (64-col strip)

    float acc[2][8][4];
#pragma unroll
    for (int mt = 0; mt < 2; mt++)
#pragma unroll
        for (int nt = 0; nt < 8; nt++)
#pragma unroll
            for (int j = 0; j < 4; j++) acc[mt][nt][j] = 0.0f;

    const int lrow  = (lid & 7) + ((lid >> 3) & 1) * 8;
    const int lhalf = lid >> 4;

    copy_tiles_f(Ah, Al, Wh, Wl, m0, n0, 0, abase, tid);
    CP_COMMIT();

    for (int kb = 0; kb < NKB_F; kb++) {
        const uint32_t sbase = abase + (uint32_t)(kb & 1) * STAGE_F;
        if (kb + 1 < NKB_F) {
            copy_tiles_f(Ah, Al, Wh, Wl, m0, n0, kb + 1,
                         abase + (uint32_t)((kb + 1) & 1) * STAGE_F, tid);
            CP_COMMIT();
            CP_WAIT(1);
        } else {
            CP_WAIT(0);
        }
        __syncthreads();

#pragma unroll
        for (int ks = 0; ks < 2; ks++) {
            const int chunk = ks * 2 + lhalf;
            uint32_t ah[2][4], al[2][4];
#pragma unroll
            for (int mt = 0; mt < 2; mt++) {
                uint32_t aoff = swz64(wm * 32 + mt * 16 + lrow, chunk);
                ldm4(ah[mt], sbase + aoff);
                ldm4(al[mt], sbase + FSTG + aoff);
            }
#pragma unroll
            for (int nt = 0; nt < 4; nt++) {
                uint32_t boff = swz64(wn * 64 + nt * 16 + lrow, chunk);
                uint32_t bh[4], bl[4];
                ldm4(bh, sbase + 2 * FSTG + boff);
                ldm4(bl, sbase + 3 * FSTG + boff);
#pragma unroll
                for (int mt = 0; mt < 2; mt++) {
                    mma_bf16(acc[mt][2 * nt + 0], ah[mt], bh[0], bh[2]);
                    mma_bf16(acc[mt][2 * nt + 1], ah[mt], bh[1], bh[3]);
                    mma_bf16(acc[mt][2 * nt + 0], ah[mt], bl[0], bl[2]);
                    mma_bf16(acc[mt][2 * nt + 1], ah[mt], bl[1], bl[3]);
                    mma_bf16(acc[mt][2 * nt + 0], al[mt], bh[0], bh[2]);
                    mma_bf16(acc[mt][2 * nt + 1], al[mt], bh[1], bh[3]);
                }
            }
        }
        __syncthreads();
    }

#pragma unroll
    for (int mt = 0; mt < 2; mt++) {
        int r0 = m0 + wm * 32 + mt * 16 + (lid >> 2);
#pragma unroll
        for (int nt = 0; nt < 8; nt++) {
            int c0 = n0 + wn * 64 + nt * 8 + (lid & 3) * 2;
            float bb0 = bias[c0], bb1 = bias[c0 + 1];
            float u0 = (acc[mt][nt][0] + bb0) * scale;
            float u1 = (acc[mt][nt][1] + bb1) * scale;
            float v0 = (acc[mt][nt][2] + bb0) * scale;
            float v1 = (acc[mt][nt][3] + bb1) * scale;
            size_t i0 = (size_t)r0 * DMODEL + c0;
            size_t i1 = (size_t)(r0 + 8) * DMODEL + c0;
            if (Ch) {
                uint32_t h0, l0, h1, l1;
                split2(u0, u1, h0, l0);
                split2(v0, v1, h1, l1);
                *(uint32_t*)(Ch + i0) = h0;
                *(uint32_t*)(Cl + i0) = l0;
                *(uint32_t*)(Ch + i1) = h1;
                *(uint32_t*)(Cl + i1) = l1;
            } else {
                float2 u; u.x = u0; u.y = u1;
                float2 v; v.x = v0; v.y = v1;
                *(float2*)(C + i0) = u;
                *(float2*)(C + i1) = v;
            }
        }
    }
}

// ---------------------------------------------------------------------------
// Tensor-core FlashAttention-2. QK^T: bf16x3. PV: 2-pass (ph*vh + ph*vl).
// NOW 2 CTAs/SM: Q fragments reloaded from smem each k-tile (frees 32
// persistent regs so the 128-reg cap at occupancy 2 doesn't spill the loop).
// __expf softmax, 1/sqrt(d_k) folded into Q.
// CTA = 128 q-rows x one (b,h). 8 warps x 16 q-rows. Key tiles of 64.
// ---------------------------------------------------------------------------
#define AT_STG   33792
#define AT_KVOFF 32768
#define AT_DSMEM (AT_KVOFF + 2 * AT_STG)     // 100352; x2 = 196.6KB <= 228KB

__global__ __launch_bounds__(256, 2) void attn_tc(
    const __nv_bfloat16* __restrict__ Qh_, const __nv_bfloat16* __restrict__ Ql_,
    const __nv_bfloat16* __restrict__ Kh_, const __nv_bfloat16* __restrict__ Kl_,
    const __nv_bfloat16* __restrict__ Vh_, const __nv_bfloat16* __restrict__ Vl_,
    const int* __restrict__ mask,
    __nv_bfloat16* __restrict__ Oh_, __nv_bfloat16* __restrict__ Ol_)
{
    extern __shared__ char sm[];
    const uint32_t sb = smem_u32(sm);

    const int tid = threadIdx.x;
    const int w   = tid >> 5;
    const int l   = tid & 31;
    const int bh  = blockIdx.y;
    const int b   = bh >> 4;
    const int h   = bh & 15;
    const int q0  = blockIdx.x * 128;

    const size_t rowQ  = ((size_t)(b * SEQ + q0)) * DMODEL + h * DKH;
    const size_t rowK0 = ((size_t)(b * SEQ)) * DMODEL + h * DKH;
    const int*   mg    = mask + b * SEQ;

    // --- Q tiles (hi/lo) -> smem, group 0 ---
#pragma unroll
    for (int i = 0; i < 4; i++) {
        int c   = tid + i * 256;
        int row = c >> 3;
        int c8  = c & 7;
        uint32_t sw = SWZ128(row * 128 + c8 * 16);
        cp16(sb + sw,         Qh_ + rowQ + (size_t)row * DMODEL + c8 * 8);
        cp16(sb + 16384 + sw, Ql_ + rowQ + (size_t)row * DMODEL + c8 * 8);
    }
    CP_COMMIT();

#define AT_COPY_KV(kb_, s_) do {                                                 \
    uint32_t kvb_ = sb + AT_KVOFF + (uint32_t)(s_) * AT_STG;                     \
    {                                                                            \
        int c_   = tid;                                                          \
        int row_ = c_ >> 3;                                                      \
        int c8_  = c_ & 7;                                                       \
        uint32_t sw_ = SWZ128(row_ * 128 + c8_ * 16);                            \
        size_t g_ = rowK0 + (size_t)((kb_) * 64 + row_) * DMODEL + c8_ * 8;      \
        cp16(kvb_ + sw_,         Kh_ + g_);                                      \
        cp16(kvb_ + 8192 + sw_,  Kl_ + g_);                                      \
        cp16(kvb_ + 16384 + sw_, Vh_ + g_);                                      \
        cp16(kvb_ + 24576 + sw_, Vl_ + g_);                                      \
    }                                                                            \
    {                                                                            \
        int c_   = tid + 256;                                                    \
        int row_ = c_ >> 3;                                                      \
        int c8_  = c_ & 7;                                                       \
        uint32_t sw_ = SWZ128(row_ * 128 + c8_ * 16);                            \
        size_t g_ = rowK0 + (size_t)((kb_) * 64 + row_) * DMODEL + c8_ * 8;      \
        cp16(kvb_ + sw_,         Kh_ + g_);                                      \
        cp16(kvb_ + 8192 + sw_,  Kl_ + g_);                                      \
        cp16(kvb_ + 16384 + sw_, Vh_ + g_);                                      \
        cp16(kvb_ + 24576 + sw_, Vl_ + g_);                                      \
    }                                                                            \
    if (tid < 16) cp16(kvb_ + 32768 + tid * 16, mg + (kb_) * 64 + tid * 4);      \
} while (0)

    AT_COPY_KV(0, 0);
    CP_COMMIT();

    CP_WAIT(1);
    __syncthreads();

    const int lrow = (l & 7) + ((l >> 3) & 1) * 8;
    const int lkb  = (l >> 4) * 16;
    const uint32_t qbase = sb + SWZ128(0);   // Q region base (swizzle of 0 = 0)

    float O[8][4];
    float S[8][4];
    float m0r = -INFINITY, m1r = -INFINITY, l0r = 0.0f, l1r = 0.0f;
#pragma unroll
    for (int nt = 0; nt < 8; nt++)
#pragma unroll
        for (int j = 0; j < 4; j++) O[nt][j] = 0.0f;

    for (int kb = 0; kb < SEQ / 64; kb++) {
        const int s = kb & 1;
        if (kb + 1 < SEQ / 64) {
            AT_COPY_KV(kb + 1, s ^ 1);
            CP_COMMIT();
            CP_WAIT(1);
        } else {
            CP_WAIT(0);
        }
        __syncthreads();

        const uint32_t kvb = sb + AT_KVOFF + (uint32_t)s * AT_STG;
        const char* kvc = sm + AT_KVOFF + (size_t)s * AT_STG;

        // ---- S = Q @ K^T (bf16x3); Q fragments reloaded per k-tile ----
#pragma unroll
        for (int nt = 0; nt < 8; nt++)
#pragma unroll
            for (int j = 0; j < 4; j++) S[nt][j] = 0.0f;

#pragma unroll
        for (int kt = 0; kt < 4; kt++) {
            uint32_t qa = sb + SWZ128((w * 16 + lrow) * 128 + kt * 32 + lkb);
            uint32_t qfh[4], qfl[4];
            ldm4(qfh, qa);
            ldm4(qfl, qa + 16384);
#pragma unroll
            for (int np = 0; np < 4; np++) {
                uint32_t ka = kvb + SWZ128((np * 16 + lrow) * 128 + kt * 32 + lkb);
                uint32_t kh[4], kl[4];
                ldm4(kh, ka);
                ldm4(kl, ka + 8192);
                mma_bf16(S[2 * np + 0], qfh, kh[0], kh[2]);
                mma_bf16(S[2 * np + 0], qfh, kl[0], kl[2]);
                mma_bf16(S[2 * np + 0], qfl, kh[0], kh[2]);
                mma_bf16(S[2 * np + 1], qfh, kh[1], kh[3]);
                mma_bf16(S[2 * np + 1], qfh, kl[1], kl[3]);
                mma_bf16(S[2 * np + 1], qfl, kh[1], kh[3]);
            }
        }

        // ---- mask + online softmax ----
        const int* smask = (const int*)(kvc + 32768);
        float mx0 = -INFINITY, mx1 = -INFINITY;
#pragma unroll
        for (int nt = 0; nt < 8; nt++) {
            int2 mk = *(const int2*)(smask + nt * 8 + (l & 3) * 2);
            if (mk.x == 0) { S[nt][0] = -1e9f; S[nt][2] = -1e9f; }
            if (mk.y == 0) { S[nt][1] = -1e9f; S[nt][3] = -1e9f; }
            mx0 = fmaxf(mx0, fmaxf(S[nt][0], S[nt][1]));
            mx1 = fmaxf(mx1, fmaxf(S[nt][2], S[nt][3]));
        }
        mx0 = fmaxf(mx0, __shfl_xor_sync(0xffffffffu, mx0, 1));
        mx0 = fmaxf(mx0, __shfl_xor_sync(0xffffffffu, mx0, 2));
        mx1 = fmaxf(mx1, __shfl_xor_sync(0xffffffffu, mx1, 1));
        mx1 = fmaxf(mx1, __shfl_xor_sync(0xffffffffu, mx1, 2));

        float mn0 = fmaxf(m0r, mx0);
        float mn1 = fmaxf(m1r, mx1);
        float a0 = __expf(m0r - mn0);
        float a1 = __expf(m1r - mn1);
        m0r = mn0; m1r = mn1;

        float sum0 = 0.0f, sum1 = 0.0f;
#pragma unroll
        for (int nt = 0; nt < 8; nt++) {
            S[nt][0] = __expf(S[nt][0] - mn0);
            S[nt][1] = __expf(S[nt][1] - mn0);
            S[nt][2] = __expf(S[nt][2] - mn1);
            S[nt][3] = __expf(S[nt][3] - mn1);
            sum0 += S[nt][0] + S[nt][1];
            sum1 += S[nt][2] + S[nt][3];
        }
        sum0 += __shfl_xor_sync(0xffffffffu, sum0, 1);
        sum0 += __shfl_xor_sync(0xffffffffu, sum0, 2);
        sum1 += __shfl_xor_sync(0xffffffffu, sum1, 1);
        sum1 += __shfl_xor_sync(0xffffffffu, sum1, 2);
        l0r = l0r * a0 + sum0;
        l1r = l1r * a1 + sum1;

#pragma unroll
        for (int nt = 0; nt < 8; nt++) {
            O[nt][0] *= a0; O[nt][1] *= a0;
            O[nt][2] *= a1; O[nt][3] *= a1;
        }

        // ---- O += P @ V (2-pass: ph*vh + ph*vl) ----
#pragma unroll
        for (int kt = 0; kt < 4; kt++) {
            uint32_t ph[4];
            ph[0] = pack2(S[2 * kt + 0][0], S[2 * kt + 0][1]);
            ph[1] = pack2(S[2 * kt + 0][2], S[2 * kt + 0][3]);
            ph[2] = pack2(S[2 * kt + 1][0], S[2 * kt + 1][1]);
            ph[3] = pack2(S[2 * kt + 1][2], S[2 * kt + 1][3]);
#pragma unroll
            for (int dp = 0; dp < 4; dp++) {
                uint32_t va = kvb + 16384 + SWZ128((kt * 16 + lrow) * 128 + dp * 32 + lkb);
                uint32_t vh[4], vl[4];
                ldm4t(vh, va);
                ldm4t(vl, va + 8192);
                mma_bf16(O[2 * dp + 0], ph, vh[0], vh[1]);
                mma_bf16(O[2 * dp + 0], ph, vl[0], vl[1]);
                mma_bf16(O[2 * dp + 1], ph, vh[2], vh[3]);
                mma_bf16(O[2 * dp + 1], ph, vl[2], vl[3]);
            }
        }
        __syncthreads();
    }

    // ---- epilogue: normalize, split hi/lo, store ----
    float inv0 = 1.0f / l0r;
    float inv1 = 1.0f / l1r;
    const int r0 = b * SEQ + q0 + w * 16 + (l >> 2);
#pragma unroll
    for (int nt = 0; nt < 8; nt++) {
        size_t idx = (size_t)r0 * DMODEL + h * DKH + nt * 8 + (l & 3) * 2;
        uint32_t hA, lA, hB, lB;
        split2(O[nt][0] * inv0, O[nt][1] * inv0, hA, lA);
        split2(O[nt][2] * inv1, O[nt][3] * inv1, hB, lB);
        *(uint32_t*)(Oh_ + idx)              = hA;
        *(uint32_t*)(Ol_ + idx)              = lA;
        *(uint32_t*)(Oh_ + idx + 8 * DMODEL) = hB;
        *(uint32_t*)(Ol_ + idx + 8 * DMODEL) = lB;
    }
#undef AT_COPY_KV
}

// ---------------------------------------------------------------------------
extern "C" void kernel_launch(void* const* d_in, const int* in_sizes, int n_in,
                              void* d_out, int out_size)
{
    const float* x    = (const float*)d_in[0];
    const int*   mask = (const int*)  d_in[1];
    const float* Wq   = (const float*)d_in[2];
    const float* bq   = (const float*)d_in[3];
    const float* Wk   = (const float*)d_in[4];
    const float* bk   = (const float*)d_in[5];
    const float* Wv   = (const float*)d_in[6];
    const float* bv   = (const float*)d_in[7];
    const float* Wo   = (const float*)d_in[8];
    const float* bo   = (const float*)d_in[9];
    float* out = (float*)d_out;

    __nv_bfloat16 *xh, *xl, *wh, *wl, *qh, *ql, *kh, *kl, *vh, *vl, *ah, *al;
    cudaGetSymbolAddress((void**)&xh, g_xh);
    cudaGetSymbolAddress((void**)&xl, g_xl);
    cudaGetSymbolAddress((void**)&wh, g_wh);
    cudaGetSymbolAddress((void**)&wl, g_wl);
    cudaGetSymbolAddress((void**)&qh, g_qh);
    cudaGetSymbolAddress((void**)&ql, g_ql);
    cudaGetSymbolAddress((void**)&kh, g_kh);
    cudaGetSymbolAddress((void**)&kl, g_kl);
    cudaGetSymbolAddress((void**)&vh, g_vh);
    cudaGetSymbolAddress((void**)&vl, g_vl);
    cudaGetSymbolAddress((void**)&ah, g_ah);
    cudaGetSymbolAddress((void**)&al, g_al);

    cudaFuncSetAttribute(gemm_f,
                         cudaFuncAttributeMaxDynamicSharedMemorySize, GEMM_DSMEM);
    cudaFuncSetAttribute(attn_tc,
                         cudaFuncAttributeMaxDynamicSharedMemorySize, AT_DSMEM);

    const int n4x = MR * DMODEL / 4;
    const int n4w = DD / 4;

    cvt_hilo<<<n4x / 256, 256>>>(x, xh, xl, n4x);
    dim3 gw(n4w / 256, 1, 4);
    cvt_hilo_w<<<gw, 256>>>(Wq, Wk, Wv, Wo, wh, wl, n4w);

    // merged QKV projection: z = 0/1/2 -> Q/K/V. Q gets 1/sqrt(dk) scale.
    dim3 gqkv(MR / TM, DMODEL / TN, 3);   // 64 x 8 x 3
    gemm_f<<<gqkv, 256, GEMM_DSMEM>>>(xh, xl, wh, wl, bq, bk, bv,
                                      qh, ql, kh, kl, vh, vl,
                                      nullptr, 0.125f);

    dim3 ga(SEQ / 128, BATCH * NHEADS);   // 16 x 64
    attn_tc<<<ga, 256, AT_DSMEM>>>(qh, ql, kh, kl, vh, vl, mask, ah, al);

    // output projection (z extent 1, fp32 output)
    dim3 go(MR / TM, DMODEL / TN, 1);
    gemm_f<<<go, 256, GEMM_DSMEM>>>(ah, al, wh + 3 * (size_t)DD, wl + 3 * (size_t)DD,
                                    bo, bo, bo,
                                    nullptr, nullptr, nullptr, nullptr, nullptr, nullptr,
                                    out, 1.0f);
}

// round 16
// speedup vs baseline: 1.7146x; 1.0159x over previous
#include <cuda_runtime.h>
#include <cuda_bf16.h>
#include <math.h>
#include <stdint.h>

#define DMODEL 1024
#define NHEADS 16
#define DKH    64
#define BATCH  4
#define SEQ    2048
#define MR     (BATCH * SEQ)   // 8192 rows
#define DD     (DMODEL * DMODEL)

// 1/sqrt(d_k) * log2(e), folded into Q so softmax uses ex2.approx directly
#define QSCALE 0.180336880111120426f

// ---------------- scratch (allocation-free rule: __device__ globals) -------
static __device__ __nv_bfloat16 g_xh[(size_t)MR * DMODEL];
static __device__ __nv_bfloat16 g_xl[(size_t)MR * DMODEL];
static __device__ __nv_bfloat16 g_wh[(size_t)4 * DD];
static __device__ __nv_bfloat16 g_wl[(size_t)4 * DD];
static __device__ __nv_bfloat16 g_qh[(size_t)MR * DMODEL];
static __device__ __nv_bfloat16 g_ql[(size_t)MR * DMODEL];
static __device__ __nv_bfloat16 g_kh[(size_t)MR * DMODEL];
static __device__ __nv_bfloat16 g_kl[(size_t)MR * DMODEL];
static __device__ __nv_bfloat16 g_vh[(size_t)MR * DMODEL];
static __device__ __nv_bfloat16 g_vl[(size_t)MR * DMODEL];
static __device__ __nv_bfloat16 g_ah[(size_t)MR * DMODEL];
static __device__ __nv_bfloat16 g_al[(size_t)MR * DMODEL];

// ---------------- PTX helpers (baseline, legal on compute_103) -------------
__device__ __forceinline__ uint32_t smem_u32(const void* p) {
    uint32_t a;
    asm("{ .reg .u64 t; cvta.to.shared.u64 t, %1; cvt.u32.u64 %0, t; }"
        : "=r"(a) : "l"(p));
    return a;
}

// single-MUFU base-2 exponential
__device__ __forceinline__ float fexp2(float x) {
    float y;
    asm("ex2.approx.ftz.f32 %0, %1;" : "=f"(y) : "f"(x));
    return y;
}

__device__ __forceinline__ void cp16(uint32_t dst, const void* src) {
    asm volatile("cp.async.cg.shared.global [%0], [%1], 16;\n"
                 :: "r"(dst), "l"(src) : "memory");
}
#define CP_COMMIT() asm volatile("cp.async.commit_group;\n" ::: "memory")
#define CP_WAIT(n)  asm volatile("cp.async.wait_group %0;\n" :: "n"(n) : "memory")

__device__ __forceinline__ void ldm4(uint32_t* r, uint32_t addr) {
    asm volatile("ldmatrix.sync.aligned.m8n8.x4.shared.b16 {%0,%1,%2,%3}, [%4];"
                 : "=r"(r[0]), "=r"(r[1]), "=r"(r[2]), "=r"(r[3]) : "r"(addr));
}

__device__ __forceinline__ void ldm4t(uint32_t* r, uint32_t addr) {
    asm volatile("ldmatrix.sync.aligned.m8n8.x4.trans.shared.b16 {%0,%1,%2,%3}, [%4];"
                 : "=r"(r[0]), "=r"(r[1]), "=r"(r[2]), "=r"(r[3]) : "r"(addr));
}

__device__ __forceinline__ void mma_bf16(float* c, const uint32_t* a,
                                         uint32_t b0, uint32_t b1) {
    asm volatile(
        "mma.sync.aligned.m16n8k16.row.col.f32.bf16.bf16.f32 "
        "{%0,%1,%2,%3}, {%4,%5,%6,%7}, {%8,%9}, {%0,%1,%2,%3};"
        : "+f"(c[0]), "+f"(c[1]), "+f"(c[2]), "+f"(c[3])
        : "r"(a[0]), "r"(a[1]), "r"(a[2]), "r"(a[3]), "r"(b0), "r"(b1));
}

// split fp32 pair into packed bf16 hi (truncated) + bf16 lo (rn of residual)
__device__ __forceinline__ void split2(float v0, float v1, uint32_t& h, uint32_t& l) {
    uint32_t b0 = __float_as_uint(v0), b1 = __float_as_uint(v1);
    h = __byte_perm(b0, b1, 0x7632);
    float r0 = v0 - __uint_as_float(b0 & 0xFFFF0000u);
    float r1 = v1 - __uint_as_float(b1 & 0xFFFF0000u);
    asm("cvt.rn.bf16x2.f32 %0, %1, %2;" : "=r"(l) : "f"(r1), "f"(r0));
}

// pack fp32 pair to bf16x2 (round-to-nearest, no residual)
__device__ __forceinline__ uint32_t pack2(float v0, float v1) {
    uint32_t r;
    asm("cvt.rn.bf16x2.f32 %0, %1, %2;" : "=r"(r) : "f"(v1), "f"(v0));
    return r;
}

// SW128 swizzle for 128B rows
#define SWZ128(o) ((o) ^ (((o) >> 3) & 0x70))
// swizzle for 64B rows
__device__ __forceinline__ uint32_t swz64(int row, int c16) {
    return (uint32_t)(row * 64 + ((c16 ^ ((row >> 1) & 3)) << 4));
}

// ---------------- fp32 -> (bf16 hi, bf16 lo) conversion --------------------
__global__ __launch_bounds__(256) void cvt_hilo(
    const float* __restrict__ in,
    __nv_bfloat16* __restrict__ hi, __nv_bfloat16* __restrict__ lo, int n4)
{
    int i = blockIdx.x * 256 + threadIdx.x;
    if (i >= n4) return;
    float4 v = ((const float4*)in)[i];
    uint32_t h0, l0, h1, l1;
    split2(v.x, v.y, h0, l0);
    split2(v.z, v.w, h1, l1);
    uint2 hh, ll;
    hh.x = h0; hh.y = h1;
    ll.x = l0; ll.y = l1;
    ((uint2*)hi)[i] = hh;
    ((uint2*)lo)[i] = ll;
}

// all 4 weight matrices in one launch (z selects source)
__global__ __launch_bounds__(256) void cvt_hilo_w(
    const float* __restrict__ w0, const float* __restrict__ w1,
    const float* __restrict__ w2, const float* __restrict__ w3,
    __nv_bfloat16* __restrict__ hi, __nv_bfloat16* __restrict__ lo, int n4)
{
    int i = blockIdx.x * 256 + threadIdx.x;
    if (i >= n4) return;
    const int z = blockIdx.z;
    const float* in = (z == 0) ? w0 : ((z == 1) ? w1 : ((z == 2) ? w2 : w3));
    float4 v = ((const float4*)in)[i];
    uint32_t h0, l0, h1, l1;
    split2(v.x, v.y, h0, l0);
    split2(v.z, v.w, h1, l1);
    uint2 hh, ll;
    hh.x = h0; hh.y = h1;
    ll.x = l0; ll.y = l1;
    ((uint2*)(hi + (size_t)z * DD))[i] = hh;
    ((uint2*)(lo + (size_t)z * DD))[i] = ll;
}

// ---------------- bf16x3 GEMM (mma.sync): C[M,N]=(A@W^T+bias)*scale --------
// tile 128x128, KB=32, double-buffered cp.async, 256 threads, 2 CTAs/SM
// (validated R14). UNCHANGED from R15 — at the drifted-clock HMMA ceiling.
#define TM 128
#define TN 128
#define KB_F   32
#define NKB_F  (DMODEL / KB_F)         // 32
#define FSTG   (TM * KB_F * 2)         // 8192 B per bf16 submatrix
#define STAGE_F (4 * FSTG)             // 32768
#define GEMM_DSMEM (2 * STAGE_F)       // 65536 -> 2 CTAs/SM

__device__ __forceinline__ void copy_tiles_f(
    const __nv_bfloat16* __restrict__ Ah, const __nv_bfloat16* __restrict__ Al,
    const __nv_bfloat16* __restrict__ Wh, const __nv_bfloat16* __restrict__ Wl,
    int m0, int n0, int kb, uint32_t base, int tid)
{
    const int koff = kb * KB_F;
#pragma unroll
    for (int i = 0; i < 2; i++) {
        int c   = tid + i * 256;
        int row = c >> 2;
        int c16 = c & 3;
        uint32_t sw = base + swz64(row, c16);
        cp16(sw,            Ah + (size_t)(m0 + row) * DMODEL + koff + c16 * 8);
        cp16(sw + FSTG,     Al + (size_t)(m0 + row) * DMODEL + koff + c16 * 8);
        cp16(sw + 2 * FSTG, Wh + (size_t)(n0 + row) * DMODEL + koff + c16 * 8);
        cp16(sw + 3 * FSTG, Wl + (size_t)(n0 + row) * DMODEL + koff + c16 * 8);
    }
}

__global__ __launch_bounds__(256, 2) void gemm_f(
    const __nv_bfloat16* __restrict__ Ah, const __nv_bfloat16* __restrict__ Al,
    const __nv_bfloat16* __restrict__ Wh0, const __nv_bfloat16* __restrict__ Wl0,
    const float* __restrict__ b0p, const float* __restrict__ b1p,
    const float* __restrict__ b2p,
    __nv_bfloat16* __restrict__ Ch0, __nv_bfloat16* __restrict__ Cl0,
    __nv_bfloat16* __restrict__ Ch1, __nv_bfloat16* __restrict__ Cl1,
    __nv_bfloat16* __restrict__ Ch2, __nv_bfloat16* __restrict__ Cl2,
    float* __restrict__ C, float scale0)
{
    extern __shared__ char dsm[];
    const int tid = threadIdx.x;
    const int wid = tid >> 5;
    const int lid = tid & 31;
    const int m0  = blockIdx.x * TM;
    const int n0  = blockIdx.y * TN;
    const int z   = blockIdx.z;

    const __nv_bfloat16* Wh = Wh0 + (size_t)z * DD;
    const __nv_bfloat16* Wl = Wl0 + (size_t)z * DD;
    const float* bias = (z == 0) ? b0p : ((z == 1) ? b1p : b2p);
    __nv_bfloat16* Ch = (z == 0) ? Ch0 : ((z == 1) ? Ch1 : Ch2);
    __nv_bfloat16* Cl = (z == 0) ? Cl0 : ((z == 1) ? Cl1 : Cl2);
    const float scale = (z == 0) ? scale0 : 1.0f;

    const uint32_t abase = smem_u32(dsm);

    const int wm = wid >> 1;   // 0..3 (32-row strip)
    const int wn = wid & 1;    // 0..1 (64-col strip)

    float acc[2][8][4];
#pragma unroll
    for (int mt = 0; mt < 2; mt++)
#pragma unroll
        for (int nt = 0; nt < 8; nt++)
#pragma unroll
            for (int j = 0; j < 4; j++) acc[mt][nt][j] = 0.0f;

    const int lrow  = (lid & 7) + ((lid >> 3) & 1) * 8;
    const int lhalf = lid >> 4;

    copy_tiles_f(Ah, Al, Wh, Wl, m0, n0, 0, abase, tid);
    CP_COMMIT();

    for (int kb = 0; kb < NKB_F; kb++) {
        const uint32_t sbase = abase + (uint32_t)(kb & 1) * STAGE_F;
        if (kb + 1 < NKB_F) {
            copy_tiles_f(Ah, Al, Wh, Wl, m0, n0, kb + 1,
                         abase + (uint32_t)((kb + 1) & 1) * STAGE_F, tid);
            CP_COMMIT();
            CP_WAIT(1);
        } else {
            CP_WAIT(0);
        }
        __syncthreads();

#pragma unroll
        for (int ks = 0; ks < 2; ks++) {
            const int chunk = ks * 2 + lhalf;
            uint32_t ah[2][4], al[2][4];
#pragma unroll
            for (int mt = 0; mt < 2; mt++) {
                uint32_t aoff = swz64(wm * 32 + mt * 16 + lrow, chunk);
                ldm4(ah[mt], sbase + aoff);
                ldm4(al[mt], sbase + FSTG + aoff);
            }
#pragma unroll
            for (int nt = 0; nt < 4; nt++) {
                uint32_t boff = swz64(wn * 64 + nt * 16 + lrow, chunk);
                uint32_t bh[4], bl[4];
                ldm4(bh, sbase + 2 * FSTG + boff);
                ldm4(bl, sbase + 3 * FSTG + boff);
#pragma unroll
                for (int mt = 0; mt < 2; mt++) {
                    mma_bf16(acc[mt][2 * nt + 0], ah[mt], bh[0], bh[2]);
                    mma_bf16(acc[mt][2 * nt + 1], ah[mt], bh[1], bh[3]);
                    mma_bf16(acc[mt][2 * nt + 0], ah[mt], bl[0], bl[2]);
                    mma_bf16(acc[mt][2 * nt + 1], ah[mt], bl[1], bl[3]);
                    mma_bf16(acc[mt][2 * nt + 0], al[mt], bh[0], bh[2]);
                    mma_bf16(acc[mt][2 * nt + 1], al[mt], bh[1], bh[3]);
                }
            }
        }
        __syncthreads();
    }

#pragma unroll
    for (int mt = 0; mt < 2; mt++) {
        int r0 = m0 + wm * 32 + mt * 16 + (lid >> 2);
#pragma unroll
        for (int nt = 0; nt < 8; nt++) {
            int c0 = n0 + wn * 64 + nt * 8 + (lid & 3) * 2;
            float bb0 = bias[c0], bb1 = bias[c0 + 1];
            float u0 = (acc[mt][nt][0] + bb0) * scale;
            float u1 = (acc[mt][nt][1] + bb1) * scale;
            float v0 = (acc[mt][nt][2] + bb0) * scale;
            float v1 = (acc[mt][nt][3] + bb1) * scale;
            size_t i0 = (size_t)r0 * DMODEL + c0;
            size_t i1 = (size_t)(r0 + 8) * DMODEL + c0;
            if (Ch) {
                uint32_t h0, l0, h1, l1;
                split2(u0, u1, h0, l0);
                split2(v0, v1, h1, l1);
                *(uint32_t*)(Ch + i0) = h0;
                *(uint32_t*)(Cl + i0) = l0;
                *(uint32_t*)(Ch + i1) = h1;
                *(uint32_t*)(Cl + i1) = l1;
            } else {
                float2 u; u.x = u0; u.y = u1;
                float2 v; v.x = v0; v.y = v1;
                *(float2*)(C + i0) = u;
                *(float2*)(C + i1) = v;
            }
        }
    }
}

// ---------------------------------------------------------------------------
// Tensor-core FlashAttention-2. QK^T: bf16x3. PV: 2-pass. occ 2 (R15 win).
// NEW: swizzled addresses via base+XOR identity (SWZ(r*128+kt*32+o) =
// ((r*128+o)^x)^(kt<<5), valid because kt bits 5-6 are disjoint from r/o and
// the smem base is forced 1024-aligned) — cuts ~150 ALU ops/iter/thread.
// exp2-domain softmax via single-MUFU ex2.approx (log2e/sqrt(dk) in Q scale).
// CTA = 128 q-rows x one (b,h). 8 warps x 16 q-rows. Key tiles of 64.
// ---------------------------------------------------------------------------
#define AT_STG   33792
#define AT_KVOFF 32768
#define AT_DSMEM (AT_KVOFF + 2 * AT_STG + 1024)  // +1024 alignment slack; x2 <= 228KB

__global__ __launch_bounds__(256, 2) void attn_tc(
    const __nv_bfloat16* __restrict__ Qh_, const __nv_bfloat16* __restrict__ Ql_,
    const __nv_bfloat16* __restrict__ Kh_, const __nv_bfloat16* __restrict__ Kl_,
    const __nv_bfloat16* __restrict__ Vh_, const __nv_bfloat16* __restrict__ Vl_,
    const int* __restrict__ mask,
    __nv_bfloat16* __restrict__ Oh_, __nv_bfloat16* __restrict__ Ol_)
{
    extern __shared__ char sm[];
    const uint32_t sb0 = smem_u32(sm);
    const uint32_t sb  = (sb0 + 1023) & ~1023u;      // 1024-aligned base
    char* smA = sm + (sb - sb0);

    const int tid = threadIdx.x;
    const int w   = tid >> 5;
    const int l   = tid & 31;
    const int bh  = blockIdx.y;
    const int b   = bh >> 4;
    const int h   = bh & 15;
    const int q0  = blockIdx.x * 128;

    const size_t rowQ  = ((size_t)(b * SEQ + q0)) * DMODEL + h * DKH;
    const size_t rowK0 = ((size_t)(b * SEQ)) * DMODEL + h * DKH;
    const int*   mg    = mask + b * SEQ;

    // --- Q tiles (hi/lo) -> smem, group 0 ---
#pragma unroll
    for (int i = 0; i < 4; i++) {
        int c   = tid + i * 256;
        int row = c >> 3;
        int c8  = c & 7;
        uint32_t sw = SWZ128(row * 128 + c8 * 16);
        cp16(sb + sw,         Qh_ + rowQ + (size_t)row * DMODEL + c8 * 8);
        cp16(sb + 16384 + sw, Ql_ + rowQ + (size_t)row * DMODEL + c8 * 8);
    }
    CP_COMMIT();

#define AT_COPY_KV(kb_, s_) do {                                                 \
    uint32_t kvb_ = sb + AT_KVOFF + (uint32_t)(s_) * AT_STG;                     \
    {                                                                            \
        int c_   = tid;                                                          \
        int row_ = c_ >> 3;                                                      \
        int c8_  = c_ & 7;                                                       \
        uint32_t sw_ = SWZ128(row_ * 128 + c8_ * 16);                            \
        size_t g_ = rowK0 + (size_t)((kb_) * 64 + row_) * DMODEL + c8_ * 8;      \
        cp16(kvb_ + sw_,         Kh_ + g_);                                      \
        cp16(kvb_ + 8192 + sw_,  Kl_ + g_);                                      \
        cp16(kvb_ + 16384 + sw_, Vh_ + g_);                                      \
        cp16(kvb_ + 24576 + sw_, Vl_ + g_);                                      \
    }                                                                            \
    {                                                                            \
        int c_   = tid + 256;                                                    \
        int row_ = c_ >> 3;                                                      \
        int c8_  = c_ & 7;                                                       \
        uint32_t sw_ = SWZ128(row_ * 128 + c8_ * 16);                            \
        size_t g_ = rowK0 + (size_t)((kb_) * 64 + row_) * DMODEL + c8_ * 8;      \
        cp16(kvb_ + sw_,         Kh_ + g_);                                      \
        cp16(kvb_ + 8192 + sw_,  Kl_ + g_);                                      \
        cp16(kvb_ + 16384 + sw_, Vh_ + g_);                                      \
        cp16(kvb_ + 24576 + sw_, Vl_ + g_);                                      \
    }                                                                            \
    if (tid < 16) cp16(kvb_ + 32768 + tid * 16, mg + (kb_) * 64 + tid * 4);      \
} while (0)

    AT_COPY_KV(0, 0);
    CP_COMMIT();

    CP_WAIT(1);
    __syncthreads();

    const int lrow = (l & 7) + ((l >> 3) & 1) * 8;
    const int lkb  = (l >> 4) * 16;
    // swizzle core: cc = (lrow*128 + lkb) ^ ((lrow&7)<<4); kt/dp enter via XOR
    const uint32_t cc = (uint32_t)((lrow * 128 + lkb) ^ ((lrow & 7) << 4));
    const uint32_t qb = sb + (uint32_t)(w * 2048) + cc;   // Qh fragment base

    float O[8][4];
    float S[8][4];
    float m0r = -INFINITY, m1r = -INFINITY, l0r = 0.0f, l1r = 0.0f;
#pragma unroll
    for (int nt = 0; nt < 8; nt++)
#pragma unroll
        for (int j = 0; j < 4; j++) O[nt][j] = 0.0f;

    for (int kb = 0; kb < SEQ / 64; kb++) {
        const int s = kb & 1;
        if (kb + 1 < SEQ / 64) {
            AT_COPY_KV(kb + 1, s ^ 1);
            CP_COMMIT();
            CP_WAIT(1);
        } else {
            CP_WAIT(0);
        }
        __syncthreads();

        const uint32_t kvb = sb + AT_KVOFF + (uint32_t)s * AT_STG;
        const uint32_t kcc = kvb + cc;            // K region fragment base
        const uint32_t vcc = kvb + 16384 + cc;    // V region fragment base

        // ---- S = Q @ K^T (bf16x3), log2 domain ----
#pragma unroll
        for (int nt = 0; nt < 8; nt++)
#pragma unroll
            for (int j = 0; j < 4; j++) S[nt][j] = 0.0f;

#pragma unroll
        for (int kt = 0; kt < 4; kt++) {
            uint32_t qa = qb ^ (uint32_t)(kt << 5);
            uint32_t qfh[4], qfl[4];
            ldm4(qfh, qa);
            ldm4(qfl, qa + 16384);
#pragma unroll
            for (int np = 0; np < 4; np++) {
                uint32_t ka = (kcc + (uint32_t)(np * 2048)) ^ (uint32_t)(kt << 5);
                uint32_t kh[4], kl[4];
                ldm4(kh, ka);
                ldm4(kl, ka + 8192);
                mma_bf16(S[2 * np + 0], qfh, kh[0], kh[2]);
                mma_bf16(S[2 * np + 0], qfh, kl[0], kl[2]);
                mma_bf16(S[2 * np + 0], qfl, kh[0], kh[2]);
                mma_bf16(S[2 * np + 1], qfh, kh[1], kh[3]);
                mma_bf16(S[2 * np + 1], qfh, kl[1], kl[3]);
                mma_bf16(S[2 * np + 1], qfl, kh[1], kh[3]);
            }
        }

        // ---- mask + online softmax (base-2, single-MUFU ex2) ----
        const int* smask = (const int*)(smA + AT_KVOFF + (size_t)s * AT_STG + 32768);
        float mx0 = -INFINITY, mx1 = -INFINITY;
#pragma unroll
        for (int nt = 0; nt < 8; nt++) {
            int2 mk = *(const int2*)(smask + nt * 8 + (l & 3) * 2);
            if (mk.x == 0) { S[nt][0] = -1e9f; S[nt][2] = -1e9f; }
            if (mk.y == 0) { S[nt][1] = -1e9f; S[nt][3] = -1e9f; }
            mx0 = fmaxf(mx0, fmaxf(S[nt][0], S[nt][1]));
            mx1 = fmaxf(mx1, fmaxf(S[nt][2], S[nt][3]));
        }
        mx0 = fmaxf(mx0, __shfl_xor_sync(0xffffffffu, mx0, 1));
        mx0 = fmaxf(mx0, __shfl_xor_sync(0xffffffffu, mx0, 2));
        mx1 = fmaxf(mx1, __shfl_xor_sync(0xffffffffu, mx1, 1));
        mx1 = fmaxf(mx1, __shfl_xor_sync(0xffffffffu, mx1, 2));

        float mn0 = fmaxf(m0r, mx0);
        float mn1 = fmaxf(m1r, mx1);
        float a0 = fexp2(m0r - mn0);
        float a1 = fexp2(m1r - mn1);
        m0r = mn0; m1r = mn1;

        float sum0 = 0.0f, sum1 = 0.0f;
#pragma unroll
        for (int nt = 0; nt < 8; nt++) {
            S[nt][0] = fexp2(S[nt][0] - mn0);
            S[nt][1] = fexp2(S[nt][1] - mn0);
            S[nt][2] = fexp2(S[nt][2] - mn1);
            S[nt][3] = fexp2(S[nt][3] - mn1);
            sum0 += S[nt][0] + S[nt][1];
            sum1 += S[nt][2] + S[nt][3];
        }
        sum0 += __shfl_xor_sync(0xffffffffu, sum0, 1);
        sum0 += __shfl_xor_sync(0xffffffffu, sum0, 2);
        sum1 += __shfl_xor_sync(0xffffffffu, sum1, 1);
        sum1 += __shfl_xor_sync(0xffffffffu, sum1, 2);
        l0r = l0r * a0 + sum0;
        l1r = l1r * a1 + sum1;

#pragma unroll
        for (int nt = 0; nt < 8; nt++) {
            O[nt][0] *= a0; O[nt][1] *= a0;
            O[nt][2] *= a1; O[nt][3] *= a1;
        }

        // ---- O += P @ V (2-pass: ph*vh + ph*vl) ----
#pragma unroll
        for (int kt = 0; kt < 4; kt++) {
            uint32_t ph[4];
            ph[0] = pack2(S[2 * kt + 0][0], S[2 * kt + 0][1]);
            ph[1] = pack2(S[2 * kt + 0][2], S[2 * kt + 0][3]);
            ph[2] = pack2(S[2 * kt + 1][0], S[2 * kt + 1][1]);
            ph[3] = pack2(S[2 * kt + 1][2], S[2 * kt + 1][3]);
            const uint32_t vkt = vcc + (uint32_t)(kt * 2048);
#pragma unroll
            for (int dp = 0; dp < 4; dp++) {
                uint32_t va = vkt ^ (uint32_t)(dp << 5);
                uint32_t vh[4], vl[4];
                ldm4t(vh, va);
                ldm4t(vl, va + 8192);
                mma_bf16(O[2 * dp + 0], ph, vh[0], vh[1]);
                mma_bf16(O[2 * dp + 0], ph, vl[0], vl[1]);
                mma_bf16(O[2 * dp + 1], ph, vh[2], vh[3]);
                mma_bf16(O[2 * dp + 1], ph, vl[2], vl[3]);
            }
        }
        __syncthreads();
    }

    // ---- epilogue: normalize, split hi/lo, store ----
    float inv0 = 1.0f / l0r;
    float inv1 = 1.0f / l1r;
    const int r0 = b * SEQ + q0 + w * 16 + (l >> 2);
#pragma unroll
    for (int nt = 0; nt < 8; nt++) {
        size_t idx = (size_t)r0 * DMODEL + h * DKH + nt * 8 + (l & 3) * 2;
        uint32_t hA, lA, hB, lB;
        split2(O[nt][0] * inv0, O[nt][1] * inv0, hA, lA);
        split2(O[nt][2] * inv1, O[nt][3] * inv1, hB, lB);
        *(uint32_t*)(Oh_ + idx)              = hA;
        *(uint32_t*)(Ol_ + idx)              = lA;
        *(uint32_t*)(Oh_ + idx + 8 * DMODEL) = hB;
        *(uint32_t*)(Ol_ + idx + 8 * DMODEL) = lB;
    }
#undef AT_COPY_KV
}

// ---------------------------------------------------------------------------
extern "C" void kernel_launch(void* const* d_in, const int* in_sizes, int n_in,
                              void* d_out, int out_size)
{
    const float* x    = (const float*)d_in[0];
    const int*   mask = (const int*)  d_in[1];
    const float* Wq   = (const float*)d_in[2];
    const float* bq   = (const float*)d_in[3];
    const float* Wk   = (const float*)d_in[4];
    const float* bk   = (const float*)d_in[5];
    const float* Wv   = (const float*)d_in[6];
    const float* bv   = (const float*)d_in[7];
    const float* Wo   = (const float*)d_in[8];
    const float* bo   = (const float*)d_in[9];
    float* out = (float*)d_out;

    __nv_bfloat16 *xh, *xl, *wh, *wl, *qh, *ql, *kh, *kl, *vh, *vl, *ah, *al;
    cudaGetSymbolAddress((void**)&xh, g_xh);
    cudaGetSymbolAddress((void**)&xl, g_xl);
    cudaGetSymbolAddress((void**)&wh, g_wh);
    cudaGetSymbolAddress((void**)&wl, g_wl);
    cudaGetSymbolAddress((void**)&qh, g_qh);
    cudaGetSymbolAddress((void**)&ql, g_ql);
    cudaGetSymbolAddress((void**)&kh, g_kh);
    cudaGetSymbolAddress((void**)&kl, g_kl);
    cudaGetSymbolAddress((void**)&vh, g_vh);
    cudaGetSymbolAddress((void**)&vl, g_vl);
    cudaGetSymbolAddress((void**)&ah, g_ah);
    cudaGetSymbolAddress((void**)&al, g_al);

    cudaFuncSetAttribute(gemm_f,
                         cudaFuncAttributeMaxDynamicSharedMemorySize, GEMM_DSMEM);
    cudaFuncSetAttribute(attn_tc,
                         cudaFuncAttributeMaxDynamicSharedMemorySize, AT_DSMEM);

    const int n4x = MR * DMODEL / 4;
    const int n4w = DD / 4;

    cvt_hilo<<<n4x / 256, 256>>>(x, xh, xl, n4x);
    dim3 gw(n4w / 256, 1, 4);
    cvt_hilo_w<<<gw, 256>>>(Wq, Wk, Wv, Wo, wh, wl, n4w);

    // merged QKV projection: z = 0/1/2 -> Q/K/V. Q gets log2e/sqrt(dk) scale.
    dim3 gqkv(MR / TM, DMODEL / TN, 3);   // 64 x 8 x 3
    gemm_f<<<gqkv, 256, GEMM_DSMEM>>>(xh, xl, wh, wl, bq, bk, bv,
                                      qh, ql, kh, kl, vh, vl,
                                      nullptr, QSCALE);

    dim3 ga(SEQ / 128, BATCH * NHEADS);   // 16 x 64
    attn_tc<<<ga, 256, AT_DSMEM>>>(qh, ql, kh, kl, vh, vl, mask, ah, al);

    // output projection (z extent 1, fp32 output)
    dim3 go(MR / TM, DMODEL / TN, 1);
    gemm_f<<<go, 256, GEMM_DSMEM>>>(ah, al, wh + 3 * (size_t)DD, wl + 3 * (size_t)DD,
                                    bo, bo, bo,
                                    nullptr, nullptr, nullptr, nullptr, nullptr, nullptr,
                                    out, 1.0f);
}

// round 17
// speedup vs baseline: 1.7213x; 1.0039x over previous
#include <cuda_runtime.h>
#include <cuda_bf16.h>
#include <math.h>
#include <stdint.h>

#define DMODEL 1024
#define NHEADS 16
#define DKH    64
#define BATCH  4
#define SEQ    2048
#define MR     (BATCH * SEQ)   // 8192 rows
#define DD     (DMODEL * DMODEL)

// 1/sqrt(d_k) * log2(e), folded into Q so softmax uses ex2.approx directly
#define QSCALE 0.180336880111120426f

// ---------------- scratch (allocation-free rule: __device__ globals) -------
static __device__ __nv_bfloat16 g_xh[(size_t)MR * DMODEL];
static __device__ __nv_bfloat16 g_xl[(size_t)MR * DMODEL];
static __device__ __nv_bfloat16 g_wh[(size_t)4 * DD];
static __device__ __nv_bfloat16 g_wl[(size_t)4 * DD];
static __device__ __nv_bfloat16 g_qh[(size_t)MR * DMODEL];
static __device__ __nv_bfloat16 g_ql[(size_t)MR * DMODEL];
static __device__ __nv_bfloat16 g_kh[(size_t)MR * DMODEL];
static __device__ __nv_bfloat16 g_kl[(size_t)MR * DMODEL];
static __device__ __nv_bfloat16 g_vh[(size_t)MR * DMODEL];
static __device__ __nv_bfloat16 g_vl[(size_t)MR * DMODEL];
static __device__ __nv_bfloat16 g_ah[(size_t)MR * DMODEL];
static __device__ __nv_bfloat16 g_al[(size_t)MR * DMODEL];

// ---------------- PTX helpers (baseline, legal on compute_103) -------------
__device__ __forceinline__ uint32_t smem_u32(const void* p) {
    uint32_t a;
    asm("{ .reg .u64 t; cvta.to.shared.u64 t, %1; cvt.u32.u64 %0, t; }"
        : "=r"(a) : "l"(p));
    return a;
}

// single-MUFU base-2 exponential
__device__ __forceinline__ float fexp2(float x) {
    float y;
    asm("ex2.approx.ftz.f32 %0, %1;" : "=f"(y) : "f"(x));
    return y;
}

__device__ __forceinline__ void cp16(uint32_t dst, const void* src) {
    asm volatile("cp.async.cg.shared.global [%0], [%1], 16;\n"
                 :: "r"(dst), "l"(src) : "memory");
}
#define CP_COMMIT() asm volatile("cp.async.commit_group;\n" ::: "memory")
#define CP_WAIT(n)  asm volatile("cp.async.wait_group %0;\n" :: "n"(n) : "memory")

__device__ __forceinline__ void ldm4(uint32_t* r, uint32_t addr) {
    asm volatile("ldmatrix.sync.aligned.m8n8.x4.shared.b16 {%0,%1,%2,%3}, [%4];"
                 : "=r"(r[0]), "=r"(r[1]), "=r"(r[2]), "=r"(r[3]) : "r"(addr));
}

__device__ __forceinline__ void ldm4t(uint32_t* r, uint32_t addr) {
    asm volatile("ldmatrix.sync.aligned.m8n8.x4.trans.shared.b16 {%0,%1,%2,%3}, [%4];"
                 : "=r"(r[0]), "=r"(r[1]), "=r"(r[2]), "=r"(r[3]) : "r"(addr));
}

__device__ __forceinline__ void mma_bf16(float* c, const uint32_t* a,
                                         uint32_t b0, uint32_t b1) {
    asm volatile(
        "mma.sync.aligned.m16n8k16.row.col.f32.bf16.bf16.f32 "
        "{%0,%1,%2,%3}, {%4,%5,%6,%7}, {%8,%9}, {%0,%1,%2,%3};"
        : "+f"(c[0]), "+f"(c[1]), "+f"(c[2]), "+f"(c[3])
        : "r"(a[0]), "r"(a[1]), "r"(a[2]), "r"(a[3]), "r"(b0), "r"(b1));
}

// split fp32 pair into packed bf16 hi (truncated) + bf16 lo (rn of residual)
__device__ __forceinline__ void split2(float v0, float v1, uint32_t& h, uint32_t& l) {
    uint32_t b0 = __float_as_uint(v0), b1 = __float_as_uint(v1);
    h = __byte_perm(b0, b1, 0x7632);
    float r0 = v0 - __uint_as_float(b0 & 0xFFFF0000u);
    float r1 = v1 - __uint_as_float(b1 & 0xFFFF0000u);
    asm("cvt.rn.bf16x2.f32 %0, %1, %2;" : "=r"(l) : "f"(r1), "f"(r0));
}

// pack fp32 pair to bf16x2 (round-to-nearest, no residual)
__device__ __forceinline__ uint32_t pack2(float v0, float v1) {
    uint32_t r;
    asm("cvt.rn.bf16x2.f32 %0, %1, %2;" : "=r"(r) : "f"(v1), "f"(v0));
    return r;
}

// SW128 swizzle for 128B rows
#define SWZ128(o) ((o) ^ (((o) >> 3) & 0x70))
// swizzle for 64B rows
__device__ __forceinline__ uint32_t swz64(int row, int c16) {
    return (uint32_t)(row * 64 + ((c16 ^ ((row >> 1) & 3)) << 4));
}

// ---------------- fp32 -> (bf16 hi, bf16 lo) conversion --------------------
__global__ __launch_bounds__(256) void cvt_hilo(
    const float* __restrict__ in,
    __nv_bfloat16* __restrict__ hi, __nv_bfloat16* __restrict__ lo, int n4)
{
    int i = blockIdx.x * 256 + threadIdx.x;
    if (i >= n4) return;
    float4 v = ((const float4*)in)[i];
    uint32_t h0, l0, h1, l1;
    split2(v.x, v.y, h0, l0);
    split2(v.z, v.w, h1, l1);
    uint2 hh, ll;
    hh.x = h0; hh.y = h1;
    ll.x = l0; ll.y = l1;
    ((uint2*)hi)[i] = hh;
    ((uint2*)lo)[i] = ll;
}

// all 4 weight matrices in one launch (z selects source)
__global__ __launch_bounds__(256) void cvt_hilo_w(
    const float* __restrict__ w0, const float* __restrict__ w1,
    const float* __restrict__ w2, const float* __restrict__ w3,
    __nv_bfloat16* __restrict__ hi, __nv_bfloat16* __restrict__ lo, int n4)
{
    int i = blockIdx.x * 256 + threadIdx.x;
    if (i >= n4) return;
    const int z = blockIdx.z;
    const float* in = (z == 0) ? w0 : ((z == 1) ? w1 : ((z == 2) ? w2 : w3));
    float4 v = ((const float4*)in)[i];
    uint32_t h0, l0, h1, l1;
    split2(v.x, v.y, h0, l0);
    split2(v.z, v.w, h1, l1);
    uint2 hh, ll;
    hh.x = h0; hh.y = h1;
    ll.x = l0; ll.y = l1;
    ((uint2*)(hi + (size_t)z * DD))[i] = hh;
    ((uint2*)(lo + (size_t)z * DD))[i] = ll;
}

// ---------------- bf16x3 GEMM (mma.sync): C[M,N]=(A@W^T+bias)*scale --------
// tile 128x128, KB=32, 256 threads, 2 CTAs/SM.
// NOW 3-stage cp.async pipeline (96KB/CTA): copies issued 2 iters ahead,
// and the top-of-loop sync doubles as overwrite-safety -> 1 sync/iter.
#define TM 128
#define TN 128
#define KB_F   32
#define NKB_F  (DMODEL / KB_F)         // 32
#define FSTG   (TM * KB_F * 2)         // 8192 B per bf16 submatrix
#define STAGE_F (4 * FSTG)             // 32768
#define GEMM_DSMEM (3 * STAGE_F)       // 98304; x2 CTAs = 192KB <= 228KB

__device__ __forceinline__ void copy_tiles_f(
    const __nv_bfloat16* __restrict__ Ah, const __nv_bfloat16* __restrict__ Al,
    const __nv_bfloat16* __restrict__ Wh, const __nv_bfloat16* __restrict__ Wl,
    int m0, int n0, int kb, uint32_t base, int tid)
{
    const int koff = kb * KB_F;
#pragma unroll
    for (int i = 0; i < 2; i++) {
        int c   = tid + i * 256;
        int row = c >> 2;
        int c16 = c & 3;
        uint32_t sw = base + swz64(row, c16);
        cp16(sw,            Ah + (size_t)(m0 + row) * DMODEL + koff + c16 * 8);
        cp16(sw + FSTG,     Al + (size_t)(m0 + row) * DMODEL + koff + c16 * 8);
        cp16(sw + 2 * FSTG, Wh + (size_t)(n0 + row) * DMODEL + koff + c16 * 8);
        cp16(sw + 3 * FSTG, Wl + (size_t)(n0 + row) * DMODEL + koff + c16 * 8);
    }
}

__global__ __launch_bounds__(256, 2) void gemm_f(
    const __nv_bfloat16* __restrict__ Ah, const __nv_bfloat16* __restrict__ Al,
    const __nv_bfloat16* __restrict__ Wh0, const __nv_bfloat16* __restrict__ Wl0,
    const float* __restrict__ b0p, const float* __restrict__ b1p,
    const float* __restrict__ b2p,
    __nv_bfloat16* __restrict__ Ch0, __nv_bfloat16* __restrict__ Cl0,
    __nv_bfloat16* __restrict__ Ch1, __nv_bfloat16* __restrict__ Cl1,
    __nv_bfloat16* __restrict__ Ch2, __nv_bfloat16* __restrict__ Cl2,
    float* __restrict__ C, float scale0)
{
    extern __shared__ char dsm[];
    const int tid = threadIdx.x;
    const int wid = tid >> 5;
    const int lid = tid & 31;
    const int m0  = blockIdx.x * TM;
    const int n0  = blockIdx.y * TN;
    const int z   = blockIdx.z;

    const __nv_bfloat16* Wh = Wh0 + (size_t)z * DD;
    const __nv_bfloat16* Wl = Wl0 + (size_t)z * DD;
    const float* bias = (z == 0) ? b0p : ((z == 1) ? b1p : b2p);
    __nv_bfloat16* Ch = (z == 0) ? Ch0 : ((z == 1) ? Ch1 : Ch2);
    __nv_bfloat16* Cl = (z == 0) ? Cl0 : ((z == 1) ? Cl1 : Cl2);
    const float scale = (z == 0) ? scale0 : 1.0f;

    const uint32_t abase = smem_u32(dsm);

    const int wm = wid >> 1;   // 0..3 (32-row strip)
    const int wn = wid & 1;    // 0..1 (64-col strip)

    float acc[2][8][4];
#pragma unroll
    for (int mt = 0; mt < 2; mt++)
#pragma unroll
        for (int nt = 0; nt < 8; nt++)
#pragma unroll
            for (int j = 0; j < 4; j++) acc[mt][nt][j] = 0.0f;

    const int lrow  = (lid & 7) + ((lid >> 3) & 1) * 8;
    const int lhalf = lid >> 4;

    // 3-stage prologue: stages 0 and 1 in flight
    copy_tiles_f(Ah, Al, Wh, Wl, m0, n0, 0, abase, tid);
    CP_COMMIT();
    copy_tiles_f(Ah, Al, Wh, Wl, m0, n0, 1, abase + STAGE_F, tid);
    CP_COMMIT();

    int s = 0;          // compute stage
    int cs = 2;         // copy-target stage = (s + 2) % 3

    for (int kb = 0; kb < NKB_F; kb++) {
        if (kb + 1 < NKB_F) { CP_WAIT(1); } else { CP_WAIT(0); }
        __syncthreads();   // kb's data visible to all; stage cs free to overwrite

        if (kb + 2 < NKB_F) {
            copy_tiles_f(Ah, Al, Wh, Wl, m0, n0, kb + 2,
                         abase + (uint32_t)cs * STAGE_F, tid);
            CP_COMMIT();
        }

        const uint32_t sbase = abase + (uint32_t)s * STAGE_F;
#pragma unroll
        for (int ks = 0; ks < 2; ks++) {
            const int chunk = ks * 2 + lhalf;
            uint32_t ah[2][4], al[2][4];
#pragma unroll
            for (int mt = 0; mt < 2; mt++) {
                uint32_t aoff = swz64(wm * 32 + mt * 16 + lrow, chunk);
                ldm4(ah[mt], sbase + aoff);
                ldm4(al[mt], sbase + FSTG + aoff);
            }
#pragma unroll
            for (int nt = 0; nt < 4; nt++) {
                uint32_t boff = swz64(wn * 64 + nt * 16 + lrow, chunk);
                uint32_t bh[4], bl[4];
                ldm4(bh, sbase + 2 * FSTG + boff);
                ldm4(bl, sbase + 3 * FSTG + boff);
#pragma unroll
                for (int mt = 0; mt < 2; mt++) {
                    mma_bf16(acc[mt][2 * nt + 0], ah[mt], bh[0], bh[2]);
                    mma_bf16(acc[mt][2 * nt + 1], ah[mt], bh[1], bh[3]);
                    mma_bf16(acc[mt][2 * nt + 0], ah[mt], bl[0], bl[2]);
                    mma_bf16(acc[mt][2 * nt + 1], ah[mt], bl[1], bl[3]);
                    mma_bf16(acc[mt][2 * nt + 0], al[mt], bh[0], bh[2]);
                    mma_bf16(acc[mt][2 * nt + 1], al[mt], bh[1], bh[3]);
                }
            }
        }

        s  = (s == 2)  ? 0 : s + 1;
        cs = (cs == 2) ? 0 : cs + 1;
    }

#pragma unroll
    for (int mt = 0; mt < 2; mt++) {
        int r0 = m0 + wm * 32 + mt * 16 + (lid >> 2);
#pragma unroll
        for (int nt = 0; nt < 8; nt++) {
            int c0 = n0 + wn * 64 + nt * 8 + (lid & 3) * 2;
            float bb0 = bias[c0], bb1 = bias[c0 + 1];
            float u0 = (acc[mt][nt][0] + bb0) * scale;
            float u1 = (acc[mt][nt][1] + bb1) * scale;
            float v0 = (acc[mt][nt][2] + bb0) * scale;
            float v1 = (acc[mt][nt][3] + bb1) * scale;
            size_t i0 = (size_t)r0 * DMODEL + c0;
            size_t i1 = (size_t)(r0 + 8) * DMODEL + c0;
            if (Ch) {
                uint32_t h0, l0, h1, l1;
                split2(u0, u1, h0, l0);
                split2(v0, v1, h1, l1);
                *(uint32_t*)(Ch + i0) = h0;
                *(uint32_t*)(Cl + i0) = l0;
                *(uint32_t*)(Ch + i1) = h1;
                *(uint32_t*)(Cl + i1) = l1;
            } else {
                float2 u; u.x = u0; u.y = u1;
                float2 v; v.x = v0; v.y = v1;
                *(float2*)(C + i0) = u;
                *(float2*)(C + i1) = v;
            }
        }
    }
}

// ---------------------------------------------------------------------------
// Tensor-core FlashAttention-2 — UNCHANGED from R16 (validated config):
// bf16x3 QK^T, 2-pass PV, occ 2, XOR-identity addressing, ex2 softmax.
// ---------------------------------------------------------------------------
#define AT_STG   33792
#define AT_KVOFF 32768
#define AT_DSMEM (AT_KVOFF + 2 * AT_STG + 1024)

__global__ __launch_bounds__(256, 2) void attn_tc(
    const __nv_bfloat16* __restrict__ Qh_, const __nv_bfloat16* __restrict__ Ql_,
    const __nv_bfloat16* __restrict__ Kh_, const __nv_bfloat16* __restrict__ Kl_,
    const __nv_bfloat16* __restrict__ Vh_, const __nv_bfloat16* __restrict__ Vl_,
    const int* __restrict__ mask,
    __nv_bfloat16* __restrict__ Oh_, __nv_bfloat16* __restrict__ Ol_)
{
    extern __shared__ char sm[];
    const uint32_t sb0 = smem_u32(sm);
    const uint32_t sb  = (sb0 + 1023) & ~1023u;
    char* smA = sm + (sb - sb0);

    const int tid = threadIdx.x;
    const int w   = tid >> 5;
    const int l   = tid & 31;
    const int bh  = blockIdx.y;
    const int b   = bh >> 4;
    const int h   = bh & 15;
    const int q0  = blockIdx.x * 128;

    const size_t rowQ  = ((size_t)(b * SEQ + q0)) * DMODEL + h * DKH;
    const size_t rowK0 = ((size_t)(b * SEQ)) * DMODEL + h * DKH;
    const int*   mg    = mask + b * SEQ;

#pragma unroll
    for (int i = 0; i < 4; i++) {
        int c   = tid + i * 256;
        int row = c >> 3;
        int c8  = c & 7;
        uint32_t sw = SWZ128(row * 128 + c8 * 16);
        cp16(sb + sw,         Qh_ + rowQ + (size_t)row * DMODEL + c8 * 8);
        cp16(sb + 16384 + sw, Ql_ + rowQ + (size_t)row * DMODEL + c8 * 8);
    }
    CP_COMMIT();

#define AT_COPY_KV(kb_, s_) do {                                                 \
    uint32_t kvb_ = sb + AT_KVOFF + (uint32_t)(s_) * AT_STG;                     \
    {                                                                            \
        int c_   = tid;                                                          \
        int row_ = c_ >> 3;                                                      \
        int c8_  = c_ & 7;                                                       \
        uint32_t sw_ = SWZ128(row_ * 128 + c8_ * 16);                            \
        size_t g_ = rowK0 + (size_t)((kb_) * 64 + row_) * DMODEL + c8_ * 8;      \
        cp16(kvb_ + sw_,         Kh_ + g_);                                      \
        cp16(kvb_ + 8192 + sw_,  Kl_ + g_);                                      \
        cp16(kvb_ + 16384 + sw_, Vh_ + g_);                                      \
        cp16(kvb_ + 24576 + sw_, Vl_ + g_);                                      \
    }                                                                            \
    {                                                                            \
        int c_   = tid + 256;                                                    \
        int row_ = c_ >> 3;                                                      \
        int c8_  = c_ & 7;                                                       \
        uint32_t sw_ = SWZ128(row_ * 128 + c8_ * 16);                            \
        size_t g_ = rowK0 + (size_t)((kb_) * 64 + row_) * DMODEL + c8_ * 8;      \
        cp16(kvb_ + sw_,         Kh_ + g_);                                      \
        cp16(kvb_ + 8192 + sw_,  Kl_ + g_);                                      \
        cp16(kvb_ + 16384 + sw_, Vh_ + g_);                                      \
        cp16(kvb_ + 24576 + sw_, Vl_ + g_);                                      \
    }                                                                            \
    if (tid < 16) cp16(kvb_ + 32768 + tid * 16, mg + (kb_) * 64 + tid * 4);      \
} while (0)

    AT_COPY_KV(0, 0);
    CP_COMMIT();

    CP_WAIT(1);
    __syncthreads();

    const int lrow = (l & 7) + ((l >> 3) & 1) * 8;
    const int lkb  = (l >> 4) * 16;
    const uint32_t cc = (uint32_t)((lrow * 128 + lkb) ^ ((lrow & 7) << 4));
    const uint32_t qb = sb + (uint32_t)(w * 2048) + cc;

    float O[8][4];
    float S[8][4];
    float m0r = -INFINITY, m1r = -INFINITY, l0r = 0.0f, l1r = 0.0f;
#pragma unroll
    for (int nt = 0; nt < 8; nt++)
#pragma unroll
        for (int j = 0; j < 4; j++) O[nt][j] = 0.0f;

    for (int kb = 0; kb < SEQ / 64; kb++) {
        const int s = kb & 1;
        if (kb + 1 < SEQ / 64) {
            AT_COPY_KV(kb + 1, s ^ 1);
            CP_COMMIT();
            CP_WAIT(1);
        } else {
            CP_WAIT(0);
        }
        __syncthreads();

        const uint32_t kvb = sb + AT_KVOFF + (uint32_t)s * AT_STG;
        const uint32_t kcc = kvb + cc;
        const uint32_t vcc = kvb + 16384 + cc;

#pragma unroll
        for (int nt = 0; nt < 8; nt++)
#pragma unroll
            for (int j = 0; j < 4; j++) S[nt][j] = 0.0f;

#pragma unroll
        for (int kt = 0; kt < 4; kt++) {
            uint32_t qa = qb ^ (uint32_t)(kt << 5);
            uint32_t qfh[4], qfl[4];
            ldm4(qfh, qa);
            ldm4(qfl, qa + 16384);
#pragma unroll
            for (int np = 0; np < 4; np++) {
                uint32_t ka = (kcc + (uint32_t)(np * 2048)) ^ (uint32_t)(kt << 5);
                uint32_t kh[4], kl[4];
                ldm4(kh, ka);
                ldm4(kl, ka + 8192);
                mma_bf16(S[2 * np + 0], qfh, kh[0], kh[2]);
                mma_bf16(S[2 * np + 0], qfh, kl[0], kl[2]);
                mma_bf16(S[2 * np + 0], qfl, kh[0], kh[2]);
                mma_bf16(S[2 * np + 1], qfh, kh[1], kh[3]);
                mma_bf16(S[2 * np + 1], qfh, kl[1], kl[3]);
                mma_bf16(S[2 * np + 1], qfl, kh[1], kh[3]);
            }
        }

        const int* smask = (const int*)(smA + AT_KVOFF + (size_t)s * AT_STG + 32768);
        float mx0 = -INFINITY, mx1 = -INFINITY;
#pragma unroll
        for (int nt = 0; nt < 8; nt++) {
            int2 mk = *(const int2*)(smask + nt * 8 + (l & 3) * 2);
            if (mk.x == 0) { S[nt][0] = -1e9f; S[nt][2] = -1e9f; }
            if (mk.y == 0) { S[nt][1] = -1e9f; S[nt][3] = -1e9f; }
            mx0 = fmaxf(mx0, fmaxf(S[nt][0], S[nt][1]));
            mx1 = fmaxf(mx1, fmaxf(S[nt][2], S[nt][3]));
        }
        mx0 = fmaxf(mx0, __shfl_xor_sync(0xffffffffu, mx0, 1));
        mx0 = fmaxf(mx0, __shfl_xor_sync(0xffffffffu, mx0, 2));
        mx1 = fmaxf(mx1, __shfl_xor_sync(0xffffffffu, mx1, 1));
        mx1 = fmaxf(mx1, __shfl_xor_sync(0xffffffffu, mx1, 2));

        float mn0 = fmaxf(m0r, mx0);
        float mn1 = fmaxf(m1r, mx1);
        float a0 = fexp2(m0r - mn0);
        float a1 = fexp2(m1r - mn1);
        m0r = mn0; m1r = mn1;

        float sum0 = 0.0f, sum1 = 0.0f;
#pragma unroll
        for (int nt = 0; nt < 8; nt++) {
            S[nt][0] = fexp2(S[nt][0] - mn0);
            S[nt][1] = fexp2(S[nt][1] - mn0);
            S[nt][2] = fexp2(S[nt][2] - mn1);
            S[nt][3] = fexp2(S[nt][3] - mn1);
            sum0 += S[nt][0] + S[nt][1];
            sum1 += S[nt][2] + S[nt][3];
        }
        sum0 += __shfl_xor_sync(0xffffffffu, sum0, 1);
        sum0 += __shfl_xor_sync(0xffffffffu, sum0, 2);
        sum1 += __shfl_xor_sync(0xffffffffu, sum1, 1);
        sum1 += __shfl_xor_sync(0xffffffffu, sum1, 2);
        l0r = l0r * a0 + sum0;
        l1r = l1r * a1 + sum1;

#pragma unroll
        for (int nt = 0; nt < 8; nt++) {
            O[nt][0] *= a0; O[nt][1] *= a0;
            O[nt][2] *= a1; O[nt][3] *= a1;
        }

#pragma unroll
        for (int kt = 0; kt < 4; kt++) {
            uint32_t ph[4];
            ph[0] = pack2(S[2 * kt + 0][0], S[2 * kt + 0][1]);
            ph[1] = pack2(S[2 * kt + 0][2], S[2 * kt + 0][3]);
            ph[2] = pack2(S[2 * kt + 1][0], S[2 * kt + 1][1]);
            ph[3] = pack2(S[2 * kt + 1][2], S[2 * kt + 1][3]);
            const uint32_t vkt = vcc + (uint32_t)(kt * 2048);
#pragma unroll
            for (int dp = 0; dp < 4; dp++) {
                uint32_t va = vkt ^ (uint32_t)(dp << 5);
                uint32_t vh[4], vl[4];
                ldm4t(vh, va);
                ldm4t(vl, va + 8192);
                mma_bf16(O[2 * dp + 0], ph, vh[0], vh[1]);
                mma_bf16(O[2 * dp + 0], ph, vl[0], vl[1]);
                mma_bf16(O[2 * dp + 1], ph, vh[2], vh[3]);
                mma_bf16(O[2 * dp + 1], ph, vl[2], vl[3]);
            }
        }
        __syncthreads();
    }

    float inv0 = 1.0f / l0r;
    float inv1 = 1.0f / l1r;
    const int r0 = b * SEQ + q0 + w * 16 + (l >> 2);
#pragma unroll
    for (int nt = 0; nt < 8; nt++) {
        size_t idx = (size_t)r0 * DMODEL + h * DKH + nt * 8 + (l & 3) * 2;
        uint32_t hA, lA, hB, lB;
        split2(O[nt][0] * inv0, O[nt][1] * inv0, hA, lA);
        split2(O[nt][2] * inv1, O[nt][3] * inv1, hB, lB);
        *(uint32_t*)(Oh_ + idx)              = hA;
        *(uint32_t*)(Ol_ + idx)              = lA;
        *(uint32_t*)(Oh_ + idx + 8 * DMODEL) = hB;
        *(uint32_t*)(Ol_ + idx + 8 * DMODEL) = lB;
    }
#undef AT_COPY_KV
}

// ---------------------------------------------------------------------------
extern "C" void kernel_launch(void* const* d_in, const int* in_sizes, int n_in,
                              void* d_out, int out_size)
{
    const float* x    = (const float*)d_in[0];
    const int*   mask = (const int*)  d_in[1];
    const float* Wq   = (const float*)d_in[2];
    const float* bq   = (const float*)d_in[3];
    const float* Wk   = (const float*)d_in[4];
    const float* bk   = (const float*)d_in[5];
    const float* Wv   = (const float*)d_in[6];
    const float* bv   = (const float*)d_in[7];
    const float* Wo   = (const float*)d_in[8];
    const float* bo   = (const float*)d_in[9];
    float* out = (float*)d_out;

    __nv_bfloat16 *xh, *xl, *wh, *wl, *qh, *ql, *kh, *kl, *vh, *vl, *ah, *al;
    cudaGetSymbolAddress((void**)&xh, g_xh);
    cudaGetSymbolAddress((void**)&xl, g_xl);
    cudaGetSymbolAddress((void**)&wh, g_wh);
    cudaGetSymbolAddress((void**)&wl, g_wl);
    cudaGetSymbolAddress((void**)&qh, g_qh);
    cudaGetSymbolAddress((void**)&ql, g_ql);
    cudaGetSymbolAddress((void**)&kh, g_kh);
    cudaGetSymbolAddress((void**)&kl, g_kl);
    cudaGetSymbolAddress((void**)&vh, g_vh);
    cudaGetSymbolAddress((void**)&vl, g_vl);
    cudaGetSymbolAddress((void**)&ah, g_ah);
    cudaGetSymbolAddress((void**)&al, g_al);

    cudaFuncSetAttribute(gemm_f,
                         cudaFuncAttributeMaxDynamicSharedMemorySize, GEMM_DSMEM);
    cudaFuncSetAttribute(attn_tc,
                         cudaFuncAttributeMaxDynamicSharedMemorySize, AT_DSMEM);

    const int n4x = MR * DMODEL / 4;
    const int n4w = DD / 4;

    cvt_hilo<<<n4x / 256, 256>>>(x, xh, xl, n4x);
    dim3 gw(n4w / 256, 1, 4);
    cvt_hilo_w<<<gw, 256>>>(Wq, Wk, Wv, Wo, wh, wl, n4w);

    // merged QKV projection: z = 0/1/2 -> Q/K/V. Q gets log2e/sqrt(dk) scale.
    dim3 gqkv(MR / TM, DMODEL / TN, 3);   // 64 x 8 x 3
    gemm_f<<<gqkv, 256, GEMM_DSMEM>>>(xh, xl, wh, wl, bq, bk, bv,
                                      qh, ql, kh, kl, vh, vl,
                                      nullptr, QSCALE);

    dim3 ga(SEQ / 128, BATCH * NHEADS);   // 16 x 64
    attn_tc<<<ga, 256, AT_DSMEM>>>(qh, ql, kh, kl, vh, vl, mask, ah, al);

    // output projection (z extent 1, fp32 output)
    dim3 go(MR / TM, DMODEL / TN, 1);
    gemm_f<<<go, 256, GEMM_DSMEM>>>(ah, al, wh + 3 * (size_t)DD, wl + 3 * (size_t)DD,
                                    bo, bo, bo,
                                    nullptr, nullptr, nullptr, nullptr, nullptr, nullptr,
                                    out, 1.0f);
}